// round 8
// baseline (speedup 1.0000x reference)
#include <cuda_runtime.h>
#include <cuda_bf16.h>
#include <math.h>
#include <math_constants.h>
#include <stdint.h>

#define TOK 4096   // B*S
#define Dm  1024
#define Hh  16
#define HDim 64
#define Ff  4096
#define Ss  2048
#define NQ3 3072   // q|k|v fused width

// ---------------- fp32 scratch ----------------------------------------------
__device__ float g_qkv[TOK*NQ3];
__device__ float g_rl [TOK*64];        // router logits
__device__ float g_x2 [TOK*Dm];
__device__ float g_ctx[TOK*Dm];
__device__ float g_s1 [TOK*Ff];
__device__ int   g_node[TOK*Hh];
__device__ float g_pos [TOK*Hh];
__device__ int   g_start [32*4];
__device__ int   g_qstart[32*Ss];
__device__ int   g_orig  [32*Ss];
__device__ float g_qp[32*Ss*HDim];
__device__ float g_kp[32*Ss*HDim];
__device__ float g_vp[32*Ss*HDim];

// ---------------- int8 activations (two-level) + per-row scales --------------
__device__ char  g_hq1[TOK*Dm], g_hq0[TOK*Dm];  __device__ float g_hs[TOK];
__device__ char  g_cq1[TOK*Dm], g_cq0[TOK*Dm];  __device__ float g_cs[TOK];
__device__ char  g_sq1[TOK*Ff], g_sq0[TOK*Ff];  __device__ float g_ss[TOK];

// ---------------- int8 weights [N,K] + per-N scales --------------------------
__device__ char g_wA1 [NQ3*Dm],   g_wA0 [NQ3*Dm];   __device__ float g_wAs [NQ3];
__device__ char g_wo1 [Dm*Dm],    g_wo0 [Dm*Dm];    __device__ float g_wos [Dm];
__device__ char g_w121[2*Ff*Dm],  g_w120[2*Ff*Dm];  __device__ float g_w12s[2*Ff];
__device__ char g_w31 [Dm*Ff],    g_w30 [Dm*Ff];    __device__ float g_w3s [Dm];

// ---------------- bf16 (router path only) ------------------------------------
__device__ __nv_bfloat16 g_hh[TOK*Dm], g_hl[TOK*Dm];
__device__ __nv_bfloat16 g_wrh[128*Dm], g_wrl[128*Dm];

// ---------------- helpers -----------------------------------------------------
__device__ __forceinline__ uint32_t s2u(const void* p) {
    uint32_t a;
    asm("{ .reg .u64 t; cvta.to.shared.u64 t, %1; cvt.u32.u64 %0, t; }" : "=r"(a) : "l"(p));
    return a;
}

#define LDSM4(r, addr) \
    asm volatile("ldmatrix.sync.aligned.m8n8.x4.shared.b16 {%0,%1,%2,%3}, [%4];" \
        : "=r"((r)[0]), "=r"((r)[1]), "=r"((r)[2]), "=r"((r)[3]) : "r"(addr))

#define MMA_BF(d, a, b) \
    asm volatile("mma.sync.aligned.m16n8k16.row.col.f32.bf16.bf16.f32 " \
        "{%0,%1,%2,%3}, {%4,%5,%6,%7}, {%8,%9}, {%0,%1,%2,%3};" \
        : "+f"((d)[0]), "+f"((d)[1]), "+f"((d)[2]), "+f"((d)[3]) \
        : "r"((a)[0]), "r"((a)[1]), "r"((a)[2]), "r"((a)[3]), "r"((b)[0]), "r"((b)[1]))

#define MMA_I8(d, a, b) \
    asm volatile("mma.sync.aligned.m16n8k32.row.col.s32.s8.s8.s32 " \
        "{%0,%1,%2,%3}, {%4,%5,%6,%7}, {%8,%9}, {%0,%1,%2,%3};" \
        : "+r"((d)[0]), "+r"((d)[1]), "+r"((d)[2]), "+r"((d)[3]) \
        : "r"((a)[0]), "r"((a)[1]), "r"((a)[2]), "r"((a)[3]), "r"((b)[0]), "r"((b)[1]))

#define CPASYNC(dst, src) \
    asm volatile("cp.async.cg.shared.global [%0], [%1], 16;" :: "r"(dst), "l"(src))

// ---------------- fast exp (FMA pipe only) ----------------------------------
__device__ __forceinline__ float fexp(float x) {
    x = fminf(fmaxf(x, -87.0f), 88.0f);
    float y = x * 1.4426950408889634f;
    float n = rintf(y);
    float f = y - n;
    float p = 1.3333558146e-3f;
    p = fmaf(p, f, 9.6181291076e-3f);
    p = fmaf(p, f, 5.5504108665e-2f);
    p = fmaf(p, f, 2.4022650696e-1f);
    p = fmaf(p, f, 6.9314718056e-1f);
    p = fmaf(p, f, 1.0f);
    return p * __int_as_float(((int)n + 127) << 23);
}

// ============================================================================
// INT8 two-level GEMM. value = s * (q1*128 + q0). D = sA sB (16384 acc11 + 128 accX)
// ============================================================================
#define BUF_BYTES 40960
#define GI_SMEM   (2 * BUF_BYTES)

__global__ __launch_bounds__(256)
void gemm_i8(const char* __restrict__ A1, const char* __restrict__ A0,
             const float* __restrict__ sA,
             const char* __restrict__ B1, const char* __restrict__ B0,
             const float* __restrict__ sB,
             const float* __restrict__ R, float* __restrict__ C,
             int ldc, int K, float* __restrict__ Osw, int swiglu) {
    extern __shared__ char smraw[];
    const int tid  = threadIdx.x;
    const int lane = tid & 31, wid = tid >> 5;
    const int m0 = blockIdx.y * 128, n0 = blockIdx.x * 128;
    const int warp_m = (wid >> 2) * 64, warp_n = (wid & 3) * 32;
    const int nc = K >> 6;
    const uint32_t sb = s2u(smraw);

    const char* gA1 = A1 + (size_t)m0 * K;
    const char* gA0 = A0 + (size_t)m0 * K;
    const char* gB1 = B1 + (size_t)n0 * K;
    const char* gB0 = B0 + (size_t)n0 * K;

    int lr0 = tid >> 2,          lc0 = (tid & 3) * 16;
    int lr1 = (tid + 256) >> 2,  lc1 = lc0;

    #define ISSUE(buf, kc) do { \
        uint32_t db = sb + (buf) * BUF_BYTES; \
        size_t ko = (size_t)(kc) * 64; \
        uint32_t so0 = lr0 * 80 + lc0, so1 = lr1 * 80 + lc1; \
        size_t go0 = (size_t)lr0 * K + ko + lc0; \
        size_t go1 = (size_t)lr1 * K + ko + lc1; \
        CPASYNC(db + so0,         gA1 + go0); CPASYNC(db + so1,         gA1 + go1); \
        CPASYNC(db + 10240 + so0, gA0 + go0); CPASYNC(db + 10240 + so1, gA0 + go1); \
        CPASYNC(db + 20480 + so0, gB1 + go0); CPASYNC(db + 20480 + so1, gB1 + go1); \
        CPASYNC(db + 30720 + so0, gB0 + go0); CPASYNC(db + 30720 + so1, gB0 + go1); \
        asm volatile("cp.async.commit_group;"); \
    } while (0)

    ISSUE(0, 0);
    ISSUE(1, 1);

    int a11[4][4][4], aX[4][4][4];
    #pragma unroll
    for (int i = 0; i < 4; i++)
        #pragma unroll
        for (int j = 0; j < 4; j++)
            #pragma unroll
            for (int q = 0; q < 4; q++) { a11[i][j][q] = 0; aX[i][j][q] = 0; }

    const int a_row = (lane & 7) + ((lane >> 3) & 1) * 8;
    const int a_cb  = (lane >> 4) * 16;
    const int b_row = (lane & 7) + (lane >> 4) * 8;
    const int b_cb  = ((lane >> 3) & 1) * 16;
    const uint32_t aoff = (warp_m + a_row) * 80 + a_cb;
    const uint32_t boff = 20480 + (warp_n + b_row) * 80 + b_cb;

    #pragma unroll 1
    for (int kc = 0; kc < nc; kc++) {
        if (kc + 1 < nc) asm volatile("cp.async.wait_group 1;");
        else             asm volatile("cp.async.wait_group 0;");
        __syncthreads();
        uint32_t db = sb + (kc & 1) * BUF_BYTES;
        #pragma unroll
        for (int ks = 0; ks < 2; ks++) {
            uint32_t fa1[4][4], fb1[4][2], fb0[4][2];
            #pragma unroll
            for (int mt = 0; mt < 4; mt++)
                LDSM4(fa1[mt], db + aoff + mt * (16 * 80) + ks * 32);
            #pragma unroll
            for (int p = 0; p < 2; p++) {
                uint32_t bd = db + boff + p * (16 * 80) + ks * 32;
                LDSM4(&fb1[2 * p][0], bd);
                LDSM4(&fb0[2 * p][0], bd + 10240);
            }
            #pragma unroll
            for (int mt = 0; mt < 4; mt++)
                #pragma unroll
                for (int nt = 0; nt < 4; nt++) MMA_I8(a11[mt][nt], fa1[mt], fb1[nt]);
            #pragma unroll
            for (int mt = 0; mt < 4; mt++)
                #pragma unroll
                for (int nt = 0; nt < 4; nt++) MMA_I8(aX[mt][nt], fa1[mt], fb0[nt]);
            uint32_t fa0[4][4];
            #pragma unroll
            for (int mt = 0; mt < 4; mt++)
                LDSM4(fa0[mt], db + aoff + mt * (16 * 80) + ks * 32 + 10240);
            #pragma unroll
            for (int mt = 0; mt < 4; mt++)
                #pragma unroll
                for (int nt = 0; nt < 4; nt++) MMA_I8(aX[mt][nt], fa0[mt], fb1[nt]);
        }
        __syncthreads();
        if (kc + 2 < nc) ISSUE(kc & 1, kc + 2);
    }
    #undef ISSUE

    const int g  = lane >> 2;
    const int cc = (lane & 3) * 2;

    if (swiglu) {
        float* sm2 = (float*)smraw;               // [128][68] a2 staging
        if ((wid & 3) >= 2) {                     // w2 half (tile cols 64..127)
            #pragma unroll
            for (int mt = 0; mt < 4; mt++) {
                int row0 = warp_m + mt * 16 + g;
                float sa0 = sA[m0 + row0], sa1 = sA[m0 + row0 + 8];
                #pragma unroll
                for (int nt = 0; nt < 4; nt++) {
                    int c = warp_n - 64 + nt * 8 + cc;        // 0..63
                    float sb0 = sB[n0 + 64 + c], sb1 = sB[n0 + 64 + c + 1];
                    sm2[row0 * 68 + c]           = sa0 * sb0 * fmaf(16384.f, (float)a11[mt][nt][0], 128.f * (float)aX[mt][nt][0]);
                    sm2[row0 * 68 + c + 1]       = sa0 * sb1 * fmaf(16384.f, (float)a11[mt][nt][1], 128.f * (float)aX[mt][nt][1]);
                    sm2[(row0 + 8) * 68 + c]     = sa1 * sb0 * fmaf(16384.f, (float)a11[mt][nt][2], 128.f * (float)aX[mt][nt][2]);
                    sm2[(row0 + 8) * 68 + c + 1] = sa1 * sb1 * fmaf(16384.f, (float)a11[mt][nt][3], 128.f * (float)aX[mt][nt][3]);
                }
            }
        }
        __syncthreads();
        if ((wid & 3) < 2) {                      // w1 half (tile cols 0..63)
            size_t colbase = (size_t)blockIdx.x * 64;
            #pragma unroll
            for (int mt = 0; mt < 4; mt++) {
                float sa[2] = { sA[m0 + warp_m + mt * 16 + g], sA[m0 + warp_m + mt * 16 + g + 8] };
                #pragma unroll
                for (int rr = 0; rr < 2; rr++) {
                    int row = warp_m + mt * 16 + g + rr * 8;
                    float* op = Osw + (size_t)(m0 + row) * Ff + colbase;
                    #pragma unroll
                    for (int nt = 0; nt < 4; nt++) {
                        int c = warp_n + nt * 8 + cc;          // 0..63
                        float sb0 = sB[n0 + c], sb1 = sB[n0 + c + 1];
                        float a1a = sa[rr] * sb0 * fmaf(16384.f, (float)a11[mt][nt][rr * 2],     128.f * (float)aX[mt][nt][rr * 2]);
                        float a1b = sa[rr] * sb1 * fmaf(16384.f, (float)a11[mt][nt][rr * 2 + 1], 128.f * (float)aX[mt][nt][rr * 2 + 1]);
                        float a2a = sm2[row * 68 + c], a2b = sm2[row * 68 + c + 1];
                        float r0 = a1a / (1.f + fexp(-a1a)) * a2a;
                        float r1 = a1b / (1.f + fexp(-a1b)) * a2b;
                        *(float2*)(op + c) = make_float2(r0, r1);
                    }
                }
            }
        }
        return;
    }

    #pragma unroll
    for (int mt = 0; mt < 4; mt++) {
        int row0 = m0 + warp_m + mt * 16 + g;
        float sa0 = sA[row0], sa1 = sA[row0 + 8];
        #pragma unroll
        for (int nt = 0; nt < 4; nt++) {
            int col = n0 + warp_n + nt * 8 + cc;
            float sb0 = sB[col], sb1 = sB[col + 1];
            float2 v0 = make_float2(
                sa0 * sb0 * fmaf(16384.f, (float)a11[mt][nt][0], 128.f * (float)aX[mt][nt][0]),
                sa0 * sb1 * fmaf(16384.f, (float)a11[mt][nt][1], 128.f * (float)aX[mt][nt][1]));
            float2 v1 = make_float2(
                sa1 * sb0 * fmaf(16384.f, (float)a11[mt][nt][2], 128.f * (float)aX[mt][nt][2]),
                sa1 * sb1 * fmaf(16384.f, (float)a11[mt][nt][3], 128.f * (float)aX[mt][nt][3]));
            if (R) {
                float2 r0 = *(const float2*)(R + (size_t)row0 * ldc + col);
                float2 r1 = *(const float2*)(R + (size_t)(row0 + 8) * ldc + col);
                v0.x += r0.x; v0.y += r0.y; v1.x += r1.x; v1.y += r1.y;
            }
            *(float2*)(C + (size_t)row0 * ldc + col)       = v0;
            *(float2*)(C + (size_t)(row0 + 8) * ldc + col) = v1;
        }
    }
}

// ---------------- bf16 split GEMM (router only, 3-term) ----------------------
#define GH_SMEM (2 * BUF_BYTES)
__global__ __launch_bounds__(256, 2)
void gemm_hmma(const __nv_bfloat16* __restrict__ Ah, const __nv_bfloat16* __restrict__ Al,
               const __nv_bfloat16* __restrict__ Bh, const __nv_bfloat16* __restrict__ Bl,
               float* __restrict__ C, int Nc, int ldc, int K) {
    extern __shared__ char smraw[];
    const int tid  = threadIdx.x;
    const int lane = tid & 31, wid = tid >> 5;
    const int m0 = blockIdx.y * 128, n0 = blockIdx.x * 128;
    const int warp_m = (wid >> 2) * 64, warp_n = (wid & 3) * 32;
    const int nc = K >> 5;
    const uint32_t sb = s2u(smraw);

    const char* gA  = (const char*)Ah + (size_t)m0 * K * 2;
    const char* gAl = (const char*)Al + (size_t)m0 * K * 2;
    const char* gB  = (const char*)Bh + (size_t)n0 * K * 2;
    const char* gBl = (const char*)Bl + (size_t)n0 * K * 2;

    int lr0 = tid >> 2,          lc0 = (tid & 3) * 16;
    int lr1 = (tid + 256) >> 2,  lc1 = lc0;

    #define ISSUE(buf, kc) do { \
        uint32_t db = sb + (buf) * BUF_BYTES; \
        size_t ko = (size_t)(kc) * 64; \
        uint32_t so0 = lr0 * 80 + lc0, so1 = lr1 * 80 + lc1; \
        size_t go0 = (size_t)lr0 * (K * 2) + ko + lc0; \
        size_t go1 = (size_t)lr1 * (K * 2) + ko + lc1; \
        CPASYNC(db + so0,         gA  + go0); CPASYNC(db + so1,         gA  + go1); \
        CPASYNC(db + 10240 + so0, gAl + go0); CPASYNC(db + 10240 + so1, gAl + go1); \
        CPASYNC(db + 20480 + so0, gB  + go0); CPASYNC(db + 20480 + so1, gB  + go1); \
        CPASYNC(db + 30720 + so0, gBl + go0); CPASYNC(db + 30720 + so1, gBl + go1); \
        asm volatile("cp.async.commit_group;"); \
    } while (0)

    ISSUE(0, 0);
    ISSUE(1, 1);

    float acc[4][4][4];
    #pragma unroll
    for (int i = 0; i < 4; i++)
        #pragma unroll
        for (int j = 0; j < 4; j++)
            #pragma unroll
            for (int q = 0; q < 4; q++) acc[i][j][q] = 0.f;

    const int a_row = (lane & 7) + ((lane >> 3) & 1) * 8;
    const int a_cb  = (lane >> 4) * 16;
    const int b_row = (lane & 7) + (lane >> 4) * 8;
    const int b_cb  = ((lane >> 3) & 1) * 16;
    const uint32_t aoff = (warp_m + a_row) * 80 + a_cb;
    const uint32_t boff = 20480 + (warp_n + b_row) * 80 + b_cb;

    #pragma unroll 1
    for (int kc = 0; kc < nc; kc++) {
        if (kc + 1 < nc) asm volatile("cp.async.wait_group 1;");
        else             asm volatile("cp.async.wait_group 0;");
        __syncthreads();
        uint32_t db = sb + (kc & 1) * BUF_BYTES;
        #pragma unroll
        for (int ks = 0; ks < 2; ks++) {
            uint32_t ah[4][4], bh[4][2], bl[4][2];
            #pragma unroll
            for (int mt = 0; mt < 4; mt++)
                LDSM4(ah[mt], db + aoff + mt * (16 * 80) + ks * 32);
            #pragma unroll
            for (int p = 0; p < 2; p++) {
                uint32_t bd = db + boff + p * (16 * 80) + ks * 32;
                LDSM4(&bh[2 * p][0], bd);
                LDSM4(&bl[2 * p][0], bd + 10240);
            }
            #pragma unroll
            for (int mt = 0; mt < 4; mt++)
                #pragma unroll
                for (int nt = 0; nt < 4; nt++) MMA_BF(acc[mt][nt], ah[mt], bh[nt]);
            #pragma unroll
            for (int mt = 0; mt < 4; mt++)
                #pragma unroll
                for (int nt = 0; nt < 4; nt++) MMA_BF(acc[mt][nt], ah[mt], bl[nt]);
            uint32_t al[4][4];
            #pragma unroll
            for (int mt = 0; mt < 4; mt++)
                LDSM4(al[mt], db + aoff + mt * (16 * 80) + ks * 32 + 10240);
            #pragma unroll
            for (int mt = 0; mt < 4; mt++)
                #pragma unroll
                for (int nt = 0; nt < 4; nt++) MMA_BF(acc[mt][nt], al[mt], bh[nt]);
        }
        __syncthreads();
        if (kc + 2 < nc) ISSUE(kc & 1, kc + 2);
    }
    #undef ISSUE

    const int g  = lane >> 2;
    const int cc = (lane & 3) * 2;
    #pragma unroll
    for (int mt = 0; mt < 4; mt++) {
        int row0 = m0 + warp_m + mt * 16 + g;
        #pragma unroll
        for (int nt = 0; nt < 4; nt++) {
            int col = n0 + warp_n + nt * 8 + cc;
            if (col < Nc) {
                *(float2*)(C + (size_t)row0 * ldc + col)       = make_float2(acc[mt][nt][0], acc[mt][nt][1]);
                *(float2*)(C + (size_t)(row0 + 8) * ldc + col) = make_float2(acc[mt][nt][2], acc[mt][nt][3]);
            }
        }
    }
}

// ---------------- weight prep -------------------------------------------------
// column absmax of W[K,N] -> DEQUANT scale (absmax/16256) at remapped row
__global__ void wabs_k(const float* __restrict__ W, float* __restrict__ s,
                       int K, int N, int mode) {
    int n = blockIdx.x * 256 + threadIdx.x;
    if (n >= N) return;
    float m = 0.f;
    for (int k = 0; k < K; k++) m = fmaxf(m, fabsf(W[(size_t)k * N + n]));
    int orow = (mode == 0) ? n : ((n >> 6) * 128 + (n & 63) + ((mode == 2) ? 64 : 0));
    s[orow] = m * (1.0f / 16256.0f);           // FIX: store dequant scale, not raw absmax
}

// W[Kd,Nd] fp32 -> transposed two-level int8 [N,K]
__global__ void wsplit_i8(const float* __restrict__ W, char* __restrict__ Q1,
                          char* __restrict__ Q0, const float* __restrict__ s,
                          int Kd, int Nd, int mode) {
    __shared__ float t[32][33];
    int n0 = blockIdx.x * 32, k0 = blockIdx.y * 32;
    int tx = threadIdx.x, ty = threadIdx.y;
    #pragma unroll
    for (int i = 0; i < 4; i++)
        t[ty + i * 8][tx] = W[(size_t)(k0 + ty + i * 8) * Nd + n0 + tx];
    __syncthreads();
    #pragma unroll
    for (int i = 0; i < 4; i++) {
        int r = ty + i * 8;
        int n = n0 + r;
        int orow = (mode == 0) ? n : ((n >> 6) * 128 + (n & 63) + ((mode == 2) ? 64 : 0));
        float sv = s[orow];                    // dequant scale (absmax/16256)
        float inv = sv > 0.f ? 1.0f / sv : 0.f;  // FIX: quant scale = 1/s
        int qt = (int)rintf(t[tx][r] * inv);
        int a1 = (qt + 64) >> 7;
        int a0 = qt - (a1 << 7);
        size_t o = (size_t)orow * Kd + k0 + tx;
        Q1[o] = (char)a1;
        Q0[o] = (char)a0;
    }
}

// bf16 split for router weight
__global__ void wsplit_bf(const float* __restrict__ W, __nv_bfloat16* __restrict__ Th,
                          __nv_bfloat16* __restrict__ Tl, int Kd, int Nd) {
    __shared__ float t[32][33];
    int n0 = blockIdx.x * 32, k0 = blockIdx.y * 32;
    int tx = threadIdx.x, ty = threadIdx.y;
    #pragma unroll
    for (int i = 0; i < 4; i++)
        t[ty + i * 8][tx] = W[(size_t)(k0 + ty + i * 8) * Nd + n0 + tx];
    __syncthreads();
    #pragma unroll
    for (int i = 0; i < 4; i++) {
        int r = ty + i * 8;
        float v = t[tx][r];
        __nv_bfloat16 hb = __float2bfloat16(v);
        size_t o = (size_t)(n0 + r) * Kd + k0 + tx;
        Th[o] = hb;
        Tl[o] = __float2bfloat16(v - __bfloat162float(hb));
    }
}

// ---------------- rmsnorm -> int8 pair (+ optional bf16 split) ----------------
__global__ void rmsnorm_k(const float* __restrict__ x, const float* __restrict__ w,
                          char* __restrict__ q1, char* __restrict__ q0,
                          float* __restrict__ qs,
                          __nv_bfloat16* __restrict__ oh, __nv_bfloat16* __restrict__ ol) {
    int row = blockIdx.x;
    const float4* xr = (const float4*)(x + (size_t)row * Dm);
    float4 v = xr[threadIdx.x];
    float ssum = v.x*v.x + v.y*v.y + v.z*v.z + v.w*v.w;
    #pragma unroll
    for (int o = 16; o; o >>= 1) ssum += __shfl_xor_sync(0xffffffffu, ssum, o);
    __shared__ float sws[8];
    __shared__ float sfin[2];
    int lane = threadIdx.x & 31, wid = threadIdx.x >> 5;
    if (lane == 0) sws[wid] = ssum;
    __syncthreads();
    if (threadIdx.x == 0) {
        float t = 0.f;
        #pragma unroll
        for (int i = 0; i < 8; i++) t += sws[i];
        sfin[0] = rsqrtf(t * (1.0f / Dm) + 1e-6f);
    }
    __syncthreads();
    float inv = sfin[0];
    float4 wv = ((const float4*)w)[threadIdx.x];
    float4 o4;
    o4.x = v.x * inv * wv.x; o4.y = v.y * inv * wv.y;
    o4.z = v.z * inv * wv.z; o4.w = v.w * inv * wv.w;

    float am = fmaxf(fmaxf(fabsf(o4.x), fabsf(o4.y)), fmaxf(fabsf(o4.z), fabsf(o4.w)));
    #pragma unroll
    for (int o = 16; o; o >>= 1) am = fmaxf(am, __shfl_xor_sync(0xffffffffu, am, o));
    if (lane == 0) sws[wid] = am;
    __syncthreads();
    if (threadIdx.x == 0) {
        float t = 0.f;
        #pragma unroll
        for (int i = 0; i < 8; i++) t = fmaxf(t, sws[i]);
        sfin[1] = t > 0.f ? 16256.f / t : 0.f;
        qs[row] = t / 16256.f;
    }
    __syncthreads();
    float qi = sfin[1];
    int qtx = (int)rintf(o4.x * qi), qty = (int)rintf(o4.y * qi);
    int qtz = (int)rintf(o4.z * qi), qtw = (int)rintf(o4.w * qi);
    int hx = (qtx + 64) >> 7, hy = (qty + 64) >> 7, hz = (qtz + 64) >> 7, hw = (qtw + 64) >> 7;
    char4 c1 = make_char4((char)hx, (char)hy, (char)hz, (char)hw);
    char4 c0 = make_char4((char)(qtx - (hx << 7)), (char)(qty - (hy << 7)),
                          (char)(qtz - (hz << 7)), (char)(qtw - (hw << 7)));
    ((char4*)(q1 + (size_t)row * Dm))[threadIdx.x] = c1;
    ((char4*)(q0 + (size_t)row * Dm))[threadIdx.x] = c0;

    if (oh) {
        __nv_bfloat16 h0 = __float2bfloat16(o4.x), h1 = __float2bfloat16(o4.y);
        __nv_bfloat16 h2 = __float2bfloat16(o4.z), h3 = __float2bfloat16(o4.w);
        __nv_bfloat162 H0; H0.x = h0; H0.y = h1;
        __nv_bfloat162 H1; H1.x = h2; H1.y = h3;
        __nv_bfloat162* ph = (__nv_bfloat162*)(oh + (size_t)row * Dm);
        ph[threadIdx.x * 2]     = H0;
        ph[threadIdx.x * 2 + 1] = H1;
        __nv_bfloat162 L0, L1;
        L0.x = __float2bfloat16(o4.x - __bfloat162float(h0));
        L0.y = __float2bfloat16(o4.y - __bfloat162float(h1));
        L1.x = __float2bfloat16(o4.z - __bfloat162float(h2));
        L1.y = __float2bfloat16(o4.w - __bfloat162float(h3));
        __nv_bfloat162* pl = (__nv_bfloat162*)(ol + (size_t)row * Dm);
        pl[threadIdx.x * 2]     = L0;
        pl[threadIdx.x * 2 + 1] = L1;
    }
}

// ---------------- per-row fp32 -> two-level int8 quantization ----------------
__global__ void quant_rows(const float* __restrict__ src, char* __restrict__ q1,
                           char* __restrict__ q0, float* __restrict__ qs, int N) {
    int row = blockIdx.x;
    const float4* sp = (const float4*)(src + (size_t)row * N);
    int nv = N >> 10;
    float4 vv[4];
    float am = 0.f;
    #pragma unroll
    for (int i = 0; i < 4; i++) {
        if (i < nv) {
            vv[i] = sp[threadIdx.x + (i << 8)];
            am = fmaxf(am, fmaxf(fmaxf(fabsf(vv[i].x), fabsf(vv[i].y)),
                                 fmaxf(fabsf(vv[i].z), fabsf(vv[i].w))));
        }
    }
    #pragma unroll
    for (int o = 16; o; o >>= 1) am = fmaxf(am, __shfl_xor_sync(0xffffffffu, am, o));
    __shared__ float sws[8];
    __shared__ float sfin;
    int lane = threadIdx.x & 31, wid = threadIdx.x >> 5;
    if (lane == 0) sws[wid] = am;
    __syncthreads();
    if (threadIdx.x == 0) {
        float t = 0.f;
        #pragma unroll
        for (int i = 0; i < 8; i++) t = fmaxf(t, sws[i]);
        sfin = t > 0.f ? 16256.f / t : 0.f;
        qs[row] = t / 16256.f;
    }
    __syncthreads();
    float qi = sfin;
    #pragma unroll
    for (int i = 0; i < 4; i++) {
        if (i < nv) {
            int qtx = (int)rintf(vv[i].x * qi), qty = (int)rintf(vv[i].y * qi);
            int qtz = (int)rintf(vv[i].z * qi), qtw = (int)rintf(vv[i].w * qi);
            int hx = (qtx + 64) >> 7, hy = (qty + 64) >> 7, hz = (qtz + 64) >> 7, hw = (qtw + 64) >> 7;
            ((char4*)(q1 + (size_t)row * N))[threadIdx.x + (i << 8)] =
                make_char4((char)hx, (char)hy, (char)hz, (char)hw);
            ((char4*)(q0 + (size_t)row * N))[threadIdx.x + (i << 8)] =
                make_char4((char)(qtx - (hx << 7)), (char)(qty - (hy << 7)),
                           (char)(qtz - (hz << 7)), (char)(qtw - (hw << 7)));
        }
    }
}

// ---------------- node/pos + partition starts --------------------------------
__global__ void node_pos_k() {
    int bh = blockIdx.x;
    int b = bh >> 4, h = bh & 15;
    int t = threadIdx.x;
    __shared__ int cnts[256][4];
    __shared__ int base[256][4];
    int myn[8], posl[8];
    int local[4] = {0, 0, 0, 0};
    #pragma unroll
    for (int j = 0; j < 8; j++) {
        int s = t * 8 + j;
        int tok = b * Ss + s;
        const float* lp = g_rl + (size_t)tok * 64 + h * 4;
        float l0 = lp[0], l1 = lp[1], l2 = lp[2], l3 = lp[3];
        int n = 0; float bv = l0;
        if (l1 > bv) { bv = l1; n = 1; }
        if (l2 > bv) { bv = l2; n = 2; }
        if (l3 > bv) { bv = l3; n = 3; }
        myn[j] = n;
        posl[j] = local[n];
        local[n]++;
    }
    cnts[t][0] = local[0]; cnts[t][1] = local[1];
    cnts[t][2] = local[2]; cnts[t][3] = local[3];
    __syncthreads();
    if (t == 0) {
        int run[4] = {0, 0, 0, 0};
        for (int i = 0; i < 256; i++)
            #pragma unroll
            for (int v = 0; v < 4; v++) { base[i][v] = run[v]; run[v] += cnts[i][v]; }
        int st = 0;
        #pragma unroll
        for (int v = 0; v < 4; v++) { g_start[bh * 4 + v] = st; st += run[v]; }
    }
    __syncthreads();
    #pragma unroll
    for (int j = 0; j < 8; j++) {
        int s = t * 8 + j;
        int tok = b * Ss + s;
        int n = myn[j];
        g_node[tok * Hh + h] = n;
        g_pos[tok * Hh + h] = (float)(base[t][n] + posl[j]);
    }
}

// ---------------- permute (node partition) + RoPE ----------------------------
__global__ void permute_k() {
    int inst = blockIdx.x * 4 + (threadIdx.x >> 5);   // tok*16 + h
    int lane = threadIdx.x & 31;
    int tok = inst >> 4, h = inst & 15;
    int b = tok >> 11;
    int bh = b * 16 + h;
    int n = g_node[tok * Hh + h];
    float pos = g_pos[tok * Hh + h];
    int startn = g_start[bh * 4 + n];
    int slot = startn + (int)pos;
    const float* src = g_qkv + (size_t)tok * NQ3;
    float invf = exp2f(-(float)lane * (13.287712379549449f / 32.0f));
    float ang = pos * invf;
    float s, c;
    sincosf(ang, &s, &c);
    size_t drow = ((size_t)bh * Ss + slot) * HDim;
    float q1 = src[h * 64 + lane], q2 = src[h * 64 + lane + 32];
    g_qp[drow + lane]      = q1 * c - q2 * s;
    g_qp[drow + lane + 32] = q2 * c + q1 * s;
    float k1 = src[1024 + h * 64 + lane], k2 = src[1024 + h * 64 + lane + 32];
    g_kp[drow + lane]      = k1 * c - k2 * s;
    g_kp[drow + lane + 32] = k2 * c + k1 * s;
    g_vp[drow + lane]      = src[2048 + h * 64 + lane];
    g_vp[drow + lane + 32] = src[2048 + h * 64 + lane + 32];
    if (lane == 0) {
        g_qstart[bh * Ss + slot] = startn;
        g_orig  [bh * Ss + slot] = tok;
    }
}

// ---------------- attention: dense per-partition causal flash ----------------
#define ATTN_SMEM ((4096 + 4096 + 128 * 65) * 4)
__global__ __launch_bounds__(128)
void attn_k() {
    int bh = blockIdx.y;
    int h = bh & 15;
    int q0 = blockIdx.x * 128;
    int tid = threadIdx.x;
    int j = q0 + tid;
    size_t base = (size_t)bh * Ss;
    extern __shared__ float sm[];
    float* Ks = sm;
    float* Vs = sm + 4096;
    float* Sc = sm + 8192;

    float qreg[64];
    const float4* qp = (const float4*)(g_qp + (base + j) * HDim);
    #pragma unroll
    for (int d4 = 0; d4 < 16; d4++) {
        float4 v = qp[d4];
        qreg[d4*4+0] = v.x; qreg[d4*4+1] = v.y; qreg[d4*4+2] = v.z; qreg[d4*4+3] = v.w;
    }
    int startq = g_qstart[base + j];
    int orig   = g_orig[base + j];
    int kt0 = g_qstart[base + q0] >> 6;
    int ktE = (q0 >> 6) + 2;

    float m = -CUDART_INF_F, l = 0.f;
    float acc[64];
    #pragma unroll
    for (int d = 0; d < 64; d++) acc[d] = 0.f;

    for (int kt = kt0; kt < ktE; ++kt) {
        int kb = kt * 64;
        __syncthreads();
        for (int e = tid; e < 1024; e += 128) {
            int r = e >> 4, c = (e & 15) * 4;
            size_t srow = (base + kb + r) * HDim;
            *(float4*)&Ks[r * 64 + c] = *(const float4*)(g_kp + srow + c);
            *(float4*)&Vs[r * 64 + c] = *(const float4*)(g_vp + srow + c);
        }
        __syncthreads();

        float tmax = -CUDART_INF_F;
        #pragma unroll 1
        for (int kk = 0; kk < 64; ++kk) {
            int ki = kb + kk;
            float s = -1e30f;
            if (ki >= startq && ki <= j) {
                float s0 = 0.f, s1 = 0.f, s2 = 0.f, s3 = 0.f;
                const float4* kr = (const float4*)&Ks[kk * 64];
                #pragma unroll
                for (int d4 = 0; d4 < 16; d4++) {
                    float4 kv = kr[d4];
                    s0 = fmaf(qreg[d4*4+0], kv.x, s0);
                    s1 = fmaf(qreg[d4*4+1], kv.y, s1);
                    s2 = fmaf(qreg[d4*4+2], kv.z, s2);
                    s3 = fmaf(qreg[d4*4+3], kv.w, s3);
                }
                s = ((s0 + s1) + (s2 + s3)) * 0.125f;
            }
            Sc[tid * 65 + kk] = s;
            tmax = fmaxf(tmax, s);
        }
        if (tmax > -1e29f) {
            float nm = fmaxf(m, tmax);
            float scl = fexp(m - nm);
            l *= scl;
            #pragma unroll
            for (int d = 0; d < 64; d++) acc[d] *= scl;
            #pragma unroll 1
            for (int kk = 0; kk < 64; ++kk) {
                float p = fexp(Sc[tid * 65 + kk] - nm);
                l += p;
                const float4* vr = (const float4*)&Vs[kk * 64];
                #pragma unroll
                for (int d4 = 0; d4 < 16; d4++) {
                    float4 vv = vr[d4];
                    acc[d4*4+0] = fmaf(p, vv.x, acc[d4*4+0]);
                    acc[d4*4+1] = fmaf(p, vv.y, acc[d4*4+1]);
                    acc[d4*4+2] = fmaf(p, vv.z, acc[d4*4+2]);
                    acc[d4*4+3] = fmaf(p, vv.w, acc[d4*4+3]);
                }
            }
            m = nm;
        }
    }
    float inv = 1.f / l;
    float* op = g_ctx + (size_t)orig * Dm + h * HDim;
    #pragma unroll
    for (int d4 = 0; d4 < 16; d4++)
        *(float4*)(op + d4 * 4) = make_float4(acc[d4*4+0] * inv, acc[d4*4+1] * inv,
                                              acc[d4*4+2] * inv, acc[d4*4+3] * inv);
}

// ---------------- host launcher ----------------------------------------------
#define SYM(p, s) do { void* _t; cudaGetSymbolAddress(&_t, s); p = (decltype(p))_t; } while (0)

extern "C" void kernel_launch(void* const* d_in, const int* in_sizes, int n_in,
                              void* d_out, int out_size) {
    const float* x      = (const float*)d_in[0];
    const float* attn_w = (const float*)d_in[1];
    const float* ffn_w  = (const float*)d_in[2];
    const float* Wq     = (const float*)d_in[3];
    const float* Wk     = (const float*)d_in[4];
    const float* Wv     = (const float*)d_in[5];
    const float* Wo     = (const float*)d_in[6];
    const float* Wr     = (const float*)d_in[7];
    const float* w1     = (const float*)d_in[8];
    const float* w2     = (const float*)d_in[9];
    const float* w3     = (const float*)d_in[10];
    float* out = (float*)d_out;

    float *p_qkv, *p_rl, *p_x2, *p_ctx, *p_s1;
    SYM(p_qkv, g_qkv); SYM(p_rl, g_rl); SYM(p_x2, g_x2); SYM(p_ctx, g_ctx); SYM(p_s1, g_s1);
    char *hq1, *hq0, *cq1, *cq0, *sq1, *sq0;
    float *hs, *cs, *ss;
    SYM(hq1, g_hq1); SYM(hq0, g_hq0); SYM(hs, g_hs);
    SYM(cq1, g_cq1); SYM(cq0, g_cq0); SYM(cs, g_cs);
    SYM(sq1, g_sq1); SYM(sq0, g_sq0); SYM(ss, g_ss);
    char *wA1, *wA0, *wo1, *wo0, *w121, *w120, *w31, *w30;
    float *wAs, *wos, *w12s, *w3s;
    SYM(wA1, g_wA1); SYM(wA0, g_wA0); SYM(wAs, g_wAs);
    SYM(wo1, g_wo1); SYM(wo0, g_wo0); SYM(wos, g_wos);
    SYM(w121, g_w121); SYM(w120, g_w120); SYM(w12s, g_w12s);
    SYM(w31, g_w31); SYM(w30, g_w30); SYM(w3s, g_w3s);
    __nv_bfloat16 *p_hh, *p_hl, *wrh, *wrl;
    SYM(p_hh, g_hh); SYM(p_hl, g_hl); SYM(wrh, g_wrh); SYM(wrl, g_wrl);

    cudaFuncSetAttribute(attn_k, cudaFuncAttributeMaxDynamicSharedMemorySize, ATTN_SMEM);
    cudaFuncSetAttribute(gemm_i8, cudaFuncAttributeMaxDynamicSharedMemorySize, GI_SMEM);
    cudaFuncSetAttribute(gemm_hmma, cudaFuncAttributeMaxDynamicSharedMemorySize, GH_SMEM);

    cudaMemsetAsync(wrh + 64 * Dm, 0, 64 * Dm * sizeof(__nv_bfloat16));
    cudaMemsetAsync(wrl + 64 * Dm, 0, 64 * Dm * sizeof(__nv_bfloat16));

    wabs_k<<<Dm/256, 256>>>(Wq, wAs,        Dm, Dm, 0);
    wabs_k<<<Dm/256, 256>>>(Wk, wAs + 1024, Dm, Dm, 0);
    wabs_k<<<Dm/256, 256>>>(Wv, wAs + 2048, Dm, Dm, 0);
    wabs_k<<<Dm/256, 256>>>(Wo, wos,  Dm, Dm, 0);
    wabs_k<<<Ff/256, 256>>>(w1, w12s, Dm, Ff, 1);
    wabs_k<<<Ff/256, 256>>>(w2, w12s, Dm, Ff, 2);
    wabs_k<<<Dm/256, 256>>>(w3, w3s,  Ff, Dm, 0);

    dim3 tb(32, 8);
    wsplit_i8<<<dim3(Dm/32, Dm/32), tb>>>(Wq, wA1,            wA0,            wAs,        Dm, Dm, 0);
    wsplit_i8<<<dim3(Dm/32, Dm/32), tb>>>(Wk, wA1 + 1024*Dm,  wA0 + 1024*Dm,  wAs + 1024, Dm, Dm, 0);
    wsplit_i8<<<dim3(Dm/32, Dm/32), tb>>>(Wv, wA1 + 2048*Dm,  wA0 + 2048*Dm,  wAs + 2048, Dm, Dm, 0);
    wsplit_i8<<<dim3(Dm/32, Dm/32), tb>>>(Wo, wo1, wo0, wos, Dm, Dm, 0);
    wsplit_i8<<<dim3(Ff/32, Dm/32), tb>>>(w1, w121, w120, w12s, Dm, Ff, 1);
    wsplit_i8<<<dim3(Ff/32, Dm/32), tb>>>(w2, w121, w120, w12s, Dm, Ff, 2);
    wsplit_i8<<<dim3(Dm/32, Ff/32), tb>>>(w3, w31, w30, w3s, Ff, Dm, 0);
    wsplit_bf<<<dim3(2, Dm/32), tb>>>(Wr, wrh, wrl, Dm, 64);

    // 1. h = rmsnorm(x) -> int8 pair (+ bf16 for router)
    rmsnorm_k<<<TOK, 256>>>(x, attn_w, hq1, hq0, hs, p_hh, p_hl);

    // 2. QKV int8 GEMM ; router bf16 GEMM
    gemm_i8<<<dim3(NQ3/128, TOK/128), 256, GI_SMEM>>>(
        hq1, hq0, hs, wA1, wA0, wAs, nullptr, p_qkv, NQ3, Dm, nullptr, 0);
    gemm_hmma<<<dim3(1, TOK/128), 256, GH_SMEM>>>(p_hh, p_hl, wrh, wrl, p_rl, 64, 64, Dm);

    // 3. node/pos + partition & rope
    node_pos_k<<<32, 256>>>();
    permute_k<<<TOK * Hh / 4, 128>>>();

    // 4. partitioned causal flash attention -> ctx fp32, then quantize rows
    attn_k<<<dim3(Ss / 128, 2 * Hh), 128, ATTN_SMEM>>>();
    quant_rows<<<TOK, 256>>>(p_ctx, cq1, cq0, cs, Dm);

    // 5. x2 = x + ctx @ Wo
    gemm_i8<<<dim3(Dm/128, TOK/128), 256, GI_SMEM>>>(
        cq1, cq0, cs, wo1, wo0, wos, x, p_x2, Dm, Dm, nullptr, 0);

    // 6. h2 = rmsnorm(x2) -> int8 pair
    rmsnorm_k<<<TOK, 256>>>(p_x2, ffn_w, hq1, hq0, hs, nullptr, nullptr);

    // 7. fused w1|w2 GEMM with SwiGLU epilogue -> s1 fp32, then quantize
    gemm_i8<<<dim3(2*Ff/128, TOK/128), 256, GI_SMEM>>>(
        hq1, hq0, hs, w121, w120, w12s, nullptr, nullptr, 0, Dm, p_s1, 1);
    quant_rows<<<TOK, 256>>>(p_s1, sq1, sq0, ss, Ff);

    // 8. out = x2 + s1 @ w3
    gemm_i8<<<dim3(Dm/128, TOK/128), 256, GI_SMEM>>>(
        sq1, sq0, ss, w31, w30, w3s, p_x2, out, Dm, Ff, nullptr, 0);
}

// round 9
// speedup vs baseline: 2.6166x; 2.6166x over previous
#include <cuda_runtime.h>
#include <cuda_bf16.h>
#include <math.h>
#include <math_constants.h>
#include <stdint.h>

#define TOK 4096   // B*S
#define Dm  1024
#define Hh  16
#define HDim 64
#define Ff  4096
#define Ss  2048
#define NQKV 3200  // q(1024) k(1024) v(1024) router(64) pad(64)

// ---------------- fp32 scratch ----------------------------------------------
__device__ float g_qkvr[TOK*NQKV];
__device__ float g_x2 [TOK*Dm];
__device__ int   g_node[TOK*Hh];
__device__ float g_pos [TOK*Hh];
__device__ int   g_start [32*4];
__device__ int   g_qstart[32*Ss];
__device__ int   g_orig  [32*Ss];
__device__ float g_qp[32*Ss*HDim];
__device__ float g_kp[32*Ss*HDim];
__device__ float g_vp[32*Ss*HDim];

// ---------------- bf16 split activations ------------------------------------
__device__ __nv_bfloat16 g_hh [TOK*Dm], g_hl [TOK*Dm];
__device__ __nv_bfloat16 g_cxh[TOK*Dm], g_cxl[TOK*Dm];
__device__ __nv_bfloat16 g_s1h[TOK*Ff], g_s1l[TOK*Ff];

// ---------------- bf16 split transposed weights [N,K] -----------------------
__device__ __nv_bfloat16 g_wAh[NQKV*Dm], g_wAl[NQKV*Dm];    // Wq|Wk|Wv|Wr|0
__device__ __nv_bfloat16 g_woh[Dm*Dm],   g_wol[Dm*Dm];
__device__ __nv_bfloat16 g_w12h[2*Ff*Dm], g_w12l[2*Ff*Dm];  // w1/w2 interleaved
__device__ __nv_bfloat16 g_w3h[Dm*Ff],   g_w3l[Dm*Ff];

// ---------------- helpers -----------------------------------------------------
__device__ __forceinline__ uint32_t s2u(const void* p) {
    uint32_t a;
    asm("{ .reg .u64 t; cvta.to.shared.u64 t, %1; cvt.u32.u64 %0, t; }" : "=r"(a) : "l"(p));
    return a;
}

#define LDSM4(r, addr) \
    asm volatile("ldmatrix.sync.aligned.m8n8.x4.shared.b16 {%0,%1,%2,%3}, [%4];" \
        : "=r"((r)[0]), "=r"((r)[1]), "=r"((r)[2]), "=r"((r)[3]) : "r"(addr))

#define MMA(d, a, b) \
    asm volatile("mma.sync.aligned.m16n8k16.row.col.f32.bf16.bf16.f32 " \
        "{%0,%1,%2,%3}, {%4,%5,%6,%7}, {%8,%9}, {%0,%1,%2,%3};" \
        : "+f"((d)[0]), "+f"((d)[1]), "+f"((d)[2]), "+f"((d)[3]) \
        : "r"((a)[0]), "r"((a)[1]), "r"((a)[2]), "r"((a)[3]), "r"((b)[0]), "r"((b)[1]))

#define CPASYNC(dst, src) \
    asm volatile("cp.async.cg.shared.global [%0], [%1], 16;" :: "r"(dst), "l"(src))

// ---------------- fast exp (FMA pipe only) ----------------------------------
__device__ __forceinline__ float fexp(float x) {
    x = fminf(fmaxf(x, -87.0f), 88.0f);
    float y = x * 1.4426950408889634f;
    float n = rintf(y);
    float f = y - n;
    float p = 1.3333558146e-3f;
    p = fmaf(p, f, 9.6181291076e-3f);
    p = fmaf(p, f, 5.5504108665e-2f);
    p = fmaf(p, f, 2.4022650696e-1f);
    p = fmaf(p, f, 6.9314718056e-1f);
    p = fmaf(p, f, 1.0f);
    return p * __int_as_float(((int)n + 127) << 23);
}

// ---------------- HMMA split-bf16 GEMM, 256x128 tile, 512 threads ------------
// Buffer layout per stage: A-hi[256x80] | A-lo[256x80] | B-hi[128x80] | B-lo[128x80]
#define BUF_BYTES 61440
#define GH_SMEM   (2 * BUF_BYTES)

__global__ __launch_bounds__(512, 1)
void gemm_hmma(const __nv_bfloat16* __restrict__ Ah, const __nv_bfloat16* __restrict__ Al,
               const __nv_bfloat16* __restrict__ Bh, const __nv_bfloat16* __restrict__ Bl,
               const float* __restrict__ R, float* __restrict__ C,
               int M, int Nc, int ldc, int K,
               __nv_bfloat16* __restrict__ Oh, __nv_bfloat16* __restrict__ Ol, int swiglu) {
    extern __shared__ char smraw[];
    const int tid  = threadIdx.x;
    const int lane = tid & 31, wid = tid >> 5;           // wid 0..15
    const int m0 = blockIdx.y * 256, n0 = blockIdx.x * 128;
    const int warp_m = (wid >> 2) * 64, warp_n = (wid & 3) * 32;
    const int nc = K >> 5;
    const uint32_t sb = s2u(smraw);

    const char* gA  = (const char*)Ah + (size_t)m0 * K * 2;
    const char* gAl = (const char*)Al + (size_t)m0 * K * 2;
    const char* gB  = (const char*)Bh + (size_t)n0 * K * 2;
    const char* gBl = (const char*)Bl + (size_t)n0 * K * 2;

    const int rA0 = tid >> 2;              // 0..127
    const int rA1 = (tid + 512) >> 2;      // 128..255
    const int cc16 = (tid & 3) * 16;

    #define ISSUE(buf, kc) do { \
        uint32_t db = sb + (buf) * BUF_BYTES; \
        size_t ko = (size_t)(kc) * 64; \
        uint32_t so0 = rA0 * 80 + cc16, so1 = rA1 * 80 + cc16; \
        size_t go0 = (size_t)rA0 * (K * 2) + ko + cc16; \
        size_t go1 = (size_t)rA1 * (K * 2) + ko + cc16; \
        CPASYNC(db + so0,         gA  + go0); CPASYNC(db + so1,         gA  + go1); \
        CPASYNC(db + 20480 + so0, gAl + go0); CPASYNC(db + 20480 + so1, gAl + go1); \
        CPASYNC(db + 40960 + so0, gB  + go0); \
        CPASYNC(db + 51200 + so0, gBl + go0); \
        asm volatile("cp.async.commit_group;"); \
    } while (0)

    ISSUE(0, 0);
    ISSUE(1, 1);

    float acc[4][4][4];
    #pragma unroll
    for (int i = 0; i < 4; i++)
        #pragma unroll
        for (int j = 0; j < 4; j++)
            #pragma unroll
            for (int q = 0; q < 4; q++) acc[i][j][q] = 0.f;

    const int a_row = (lane & 7) + ((lane >> 3) & 1) * 8;
    const int a_cb  = (lane >> 4) * 16;
    const int b_row = (lane & 7) + (lane >> 4) * 8;
    const int b_cb  = ((lane >> 3) & 1) * 16;
    const uint32_t aoff = (warp_m + a_row) * 80 + a_cb;
    const uint32_t boff = 40960 + (warp_n + b_row) * 80 + b_cb;

    #pragma unroll 1
    for (int kc = 0; kc < nc; kc++) {
        if (kc + 1 < nc) asm volatile("cp.async.wait_group 1;");
        else             asm volatile("cp.async.wait_group 0;");
        __syncthreads();
        uint32_t db = sb + (kc & 1) * BUF_BYTES;
        #pragma unroll
        for (int ks = 0; ks < 2; ks++) {
            uint32_t ah[4][4], bh[4][2], bl[4][2];
            #pragma unroll
            for (int mt = 0; mt < 4; mt++)
                LDSM4(ah[mt], db + aoff + mt * (16 * 80) + ks * 32);
            #pragma unroll
            for (int p = 0; p < 2; p++) {
                uint32_t bd = db + boff + p * (16 * 80) + ks * 32;
                LDSM4(&bh[2 * p][0], bd);
                LDSM4(&bl[2 * p][0], bd + 10240);
            }
            #pragma unroll
            for (int mt = 0; mt < 4; mt++)
                #pragma unroll
                for (int nt = 0; nt < 4; nt++) MMA(acc[mt][nt], ah[mt], bh[nt]);
            #pragma unroll
            for (int mt = 0; mt < 4; mt++)
                #pragma unroll
                for (int nt = 0; nt < 4; nt++) MMA(acc[mt][nt], ah[mt], bl[nt]);
            uint32_t al[4][4];
            #pragma unroll
            for (int mt = 0; mt < 4; mt++)
                LDSM4(al[mt], db + aoff + mt * (16 * 80) + ks * 32 + 20480);
            #pragma unroll
            for (int mt = 0; mt < 4; mt++)
                #pragma unroll
                for (int nt = 0; nt < 4; nt++) MMA(acc[mt][nt], al[mt], bh[nt]);
        }
        __syncthreads();
        if (kc + 2 < nc) ISSUE(kc & 1, kc + 2);
    }
    #undef ISSUE

    const int g  = lane >> 2;
    const int cc = (lane & 3) * 2;

    if (swiglu) {
        float* sm2 = (float*)smraw;          // [256][68] fp32 staging for a2
        if ((wid & 3) >= 2) {
            #pragma unroll
            for (int mt = 0; mt < 4; mt++) {
                int row0 = warp_m + mt * 16 + g;
                #pragma unroll
                for (int nt = 0; nt < 4; nt++) {
                    int c = warp_n - 64 + nt * 8 + cc;
                    sm2[row0 * 68 + c]           = acc[mt][nt][0];
                    sm2[row0 * 68 + c + 1]       = acc[mt][nt][1];
                    sm2[(row0 + 8) * 68 + c]     = acc[mt][nt][2];
                    sm2[(row0 + 8) * 68 + c + 1] = acc[mt][nt][3];
                }
            }
        }
        __syncthreads();
        if ((wid & 3) < 2) {
            size_t colbase = (size_t)blockIdx.x * 64;
            #pragma unroll
            for (int mt = 0; mt < 4; mt++) {
                #pragma unroll
                for (int rr = 0; rr < 2; rr++) {
                    int row = warp_m + mt * 16 + g + rr * 8;
                    size_t orow = (size_t)(m0 + row) * Ff + colbase;
                    #pragma unroll
                    for (int nt = 0; nt < 4; nt++) {
                        int c = warp_n + nt * 8 + cc;
                        float a1a = acc[mt][nt][rr * 2], a1b = acc[mt][nt][rr * 2 + 1];
                        float a2a = sm2[row * 68 + c], a2b = sm2[row * 68 + c + 1];
                        float r0 = a1a / (1.f + fexp(-a1a)) * a2a;
                        float r1 = a1b / (1.f + fexp(-a1b)) * a2b;
                        __nv_bfloat16 h0 = __float2bfloat16(r0), h1 = __float2bfloat16(r1);
                        __nv_bfloat162 H; H.x = h0; H.y = h1;
                        *(__nv_bfloat162*)(Oh + orow + c) = H;
                        __nv_bfloat162 L;
                        L.x = __float2bfloat16(r0 - __bfloat162float(h0));
                        L.y = __float2bfloat16(r1 - __bfloat162float(h1));
                        *(__nv_bfloat162*)(Ol + orow + c) = L;
                    }
                }
            }
        }
        return;
    }

    #pragma unroll
    for (int mt = 0; mt < 4; mt++) {
        int row0 = m0 + warp_m + mt * 16 + g;
        #pragma unroll
        for (int nt = 0; nt < 4; nt++) {
            int col = n0 + warp_n + nt * 8 + cc;
            if (col < Nc) {
                float2 v0 = make_float2(acc[mt][nt][0], acc[mt][nt][1]);
                float2 v1 = make_float2(acc[mt][nt][2], acc[mt][nt][3]);
                if (R) {
                    float2 r0 = *(const float2*)(R + (size_t)row0 * ldc + col);
                    float2 r1 = *(const float2*)(R + (size_t)(row0 + 8) * ldc + col);
                    v0.x += r0.x; v0.y += r0.y; v1.x += r1.x; v1.y += r1.y;
                }
                *(float2*)(C + (size_t)row0 * ldc + col)       = v0;
                *(float2*)(C + (size_t)(row0 + 8) * ldc + col) = v1;
            }
        }
    }
}

// ---------------- weight transpose + bf16 split ------------------------------
// mode 0: row n -> n ; mode 1 (w1): n -> (n>>6)*128 + (n&63)
// mode 2 (w2): n -> (n>>6)*128 + 64 + (n&63). Columns n >= Nvalid produce zeros.
__global__ void wsplit_k(const float* __restrict__ W, __nv_bfloat16* __restrict__ Th,
                         __nv_bfloat16* __restrict__ Tl, int Kd, int Nd, int mode,
                         int Nvalid) {
    __shared__ float t[32][33];
    int n0 = blockIdx.x * 32, k0 = blockIdx.y * 32;
    int tx = threadIdx.x, ty = threadIdx.y;
    #pragma unroll
    for (int i = 0; i < 4; i++)
        t[ty + i * 8][tx] = (n0 + tx < Nvalid)
            ? W[(size_t)(k0 + ty + i * 8) * Nd + n0 + tx] : 0.f;
    __syncthreads();
    #pragma unroll
    for (int i = 0; i < 4; i++) {
        int r = ty + i * 8;
        int n = n0 + r;
        size_t orow = (mode == 0) ? (size_t)n
                    : (size_t)((n >> 6) * 128 + (n & 63) + ((mode == 2) ? 64 : 0));
        float v = t[tx][r];
        __nv_bfloat16 hb = __float2bfloat16(v);
        size_t o = orow * Kd + k0 + tx;
        Th[o] = hb;
        Tl[o] = __float2bfloat16(v - __bfloat162float(hb));
    }
}

// ---------------- rmsnorm -> bf16 split --------------------------------------
__global__ void rmsnorm_k(const float* __restrict__ x, const float* __restrict__ w,
                          __nv_bfloat16* __restrict__ oh, __nv_bfloat16* __restrict__ ol) {
    int row = blockIdx.x;
    const float4* xr = (const float4*)(x + (size_t)row * Dm);
    float4 v = xr[threadIdx.x];
    float ss = v.x*v.x + v.y*v.y + v.z*v.z + v.w*v.w;
    #pragma unroll
    for (int o = 16; o; o >>= 1) ss += __shfl_xor_sync(0xffffffffu, ss, o);
    __shared__ float sws[8];
    int lane = threadIdx.x & 31, wid = threadIdx.x >> 5;
    if (lane == 0) sws[wid] = ss;
    __syncthreads();
    if (threadIdx.x == 0) {
        float t = 0.f;
        #pragma unroll
        for (int i = 0; i < 8; i++) t += sws[i];
        sws[0] = rsqrtf(t * (1.0f / Dm) + 1e-6f);
    }
    __syncthreads();
    float inv = sws[0];
    float4 wv = ((const float4*)w)[threadIdx.x];
    float4 o4;
    o4.x = v.x * inv * wv.x; o4.y = v.y * inv * wv.y;
    o4.z = v.z * inv * wv.z; o4.w = v.w * inv * wv.w;
    __nv_bfloat16 h0 = __float2bfloat16(o4.x), h1 = __float2bfloat16(o4.y);
    __nv_bfloat16 h2 = __float2bfloat16(o4.z), h3 = __float2bfloat16(o4.w);
    __nv_bfloat162 H0; H0.x = h0; H0.y = h1;
    __nv_bfloat162 H1; H1.x = h2; H1.y = h3;
    __nv_bfloat162* ph = (__nv_bfloat162*)(oh + (size_t)row * Dm);
    ph[threadIdx.x * 2]     = H0;
    ph[threadIdx.x * 2 + 1] = H1;
    __nv_bfloat162 L0, L1;
    L0.x = __float2bfloat16(o4.x - __bfloat162float(h0));
    L0.y = __float2bfloat16(o4.y - __bfloat162float(h1));
    L1.x = __float2bfloat16(o4.z - __bfloat162float(h2));
    L1.y = __float2bfloat16(o4.w - __bfloat162float(h3));
    __nv_bfloat162* pl = (__nv_bfloat162*)(ol + (size_t)row * Dm);
    pl[threadIdx.x * 2]     = L0;
    pl[threadIdx.x * 2 + 1] = L1;
}

// ---------------- node/pos + partition starts --------------------------------
__global__ void node_pos_k() {
    int bh = blockIdx.x;
    int b = bh >> 4, h = bh & 15;
    int t = threadIdx.x;
    __shared__ int cnts[256][4];
    __shared__ int base[256][4];
    int myn[8], posl[8];
    int local[4] = {0, 0, 0, 0};
    #pragma unroll
    for (int j = 0; j < 8; j++) {
        int s = t * 8 + j;
        int tok = b * Ss + s;
        const float* lp = g_qkvr + (size_t)tok * NQKV + 3072 + h * 4;
        float l0 = lp[0], l1 = lp[1], l2 = lp[2], l3 = lp[3];
        int n = 0; float bv = l0;
        if (l1 > bv) { bv = l1; n = 1; }
        if (l2 > bv) { bv = l2; n = 2; }
        if (l3 > bv) { bv = l3; n = 3; }
        myn[j] = n;
        posl[j] = local[n];
        local[n]++;
    }
    cnts[t][0] = local[0]; cnts[t][1] = local[1];
    cnts[t][2] = local[2]; cnts[t][3] = local[3];
    __syncthreads();
    if (t == 0) {
        int run[4] = {0, 0, 0, 0};
        for (int i = 0; i < 256; i++)
            #pragma unroll
            for (int v = 0; v < 4; v++) { base[i][v] = run[v]; run[v] += cnts[i][v]; }
        int st = 0;
        #pragma unroll
        for (int v = 0; v < 4; v++) { g_start[bh * 4 + v] = st; st += run[v]; }
    }
    __syncthreads();
    #pragma unroll
    for (int j = 0; j < 8; j++) {
        int s = t * 8 + j;
        int tok = b * Ss + s;
        int n = myn[j];
        g_node[tok * Hh + h] = n;
        g_pos[tok * Hh + h] = (float)(base[t][n] + posl[j]);
    }
}

// ---------------- permute (node partition) + RoPE ----------------------------
__global__ void permute_k() {
    int inst = blockIdx.x * 4 + (threadIdx.x >> 5);   // tok*16 + h
    int lane = threadIdx.x & 31;
    int tok = inst >> 4, h = inst & 15;
    int b = tok >> 11;
    int bh = b * 16 + h;
    int n = g_node[tok * Hh + h];
    float pos = g_pos[tok * Hh + h];
    int startn = g_start[bh * 4 + n];
    int slot = startn + (int)pos;
    const float* src = g_qkvr + (size_t)tok * NQKV;
    float invf = exp2f(-(float)lane * (13.287712379549449f / 32.0f));
    float ang = pos * invf;
    float s, c;
    sincosf(ang, &s, &c);
    size_t drow = ((size_t)bh * Ss + slot) * HDim;
    float q1 = src[h * 64 + lane], q2 = src[h * 64 + lane + 32];
    g_qp[drow + lane]      = q1 * c - q2 * s;
    g_qp[drow + lane + 32] = q2 * c + q1 * s;
    float k1 = src[1024 + h * 64 + lane], k2 = src[1024 + h * 64 + lane + 32];
    g_kp[drow + lane]      = k1 * c - k2 * s;
    g_kp[drow + lane + 32] = k2 * c + k1 * s;
    g_vp[drow + lane]      = src[2048 + h * 64 + lane];
    g_vp[drow + lane + 32] = src[2048 + h * 64 + lane + 32];
    if (lane == 0) {
        g_qstart[bh * Ss + slot] = startn;
        g_orig  [bh * Ss + slot] = tok;
    }
}

// ---------------- attention: dense per-partition causal flash ----------------
#define ATTN_SMEM ((4096 + 4096 + 128 * 65) * 4)
__global__ __launch_bounds__(128)
void attn_k() {
    int bh = blockIdx.y;
    int h = bh & 15;
    int q0 = blockIdx.x * 128;
    int tid = threadIdx.x;
    int j = q0 + tid;
    size_t base = (size_t)bh * Ss;
    extern __shared__ float sm[];
    float* Ks = sm;
    float* Vs = sm + 4096;
    float* Sc = sm + 8192;

    float qreg[64];
    const float4* qp = (const float4*)(g_qp + (base + j) * HDim);
    #pragma unroll
    for (int d4 = 0; d4 < 16; d4++) {
        float4 v = qp[d4];
        qreg[d4*4+0] = v.x; qreg[d4*4+1] = v.y; qreg[d4*4+2] = v.z; qreg[d4*4+3] = v.w;
    }
    int startq = g_qstart[base + j];
    int orig   = g_orig[base + j];
    int kt0 = g_qstart[base + q0] >> 6;
    int ktE = (q0 >> 6) + 2;

    float m = -CUDART_INF_F, l = 0.f;
    float acc[64];
    #pragma unroll
    for (int d = 0; d < 64; d++) acc[d] = 0.f;

    for (int kt = kt0; kt < ktE; ++kt) {
        int kb = kt * 64;
        __syncthreads();
        for (int e = tid; e < 1024; e += 128) {
            int r = e >> 4, c = (e & 15) * 4;
            size_t srow = (base + kb + r) * HDim;
            *(float4*)&Ks[r * 64 + c] = *(const float4*)(g_kp + srow + c);
            *(float4*)&Vs[r * 64 + c] = *(const float4*)(g_vp + srow + c);
        }
        __syncthreads();

        float tmax = -CUDART_INF_F;
        #pragma unroll 1
        for (int kk = 0; kk < 64; ++kk) {
            int ki = kb + kk;
            float s = -1e30f;
            if (ki >= startq && ki <= j) {
                float s0 = 0.f, s1 = 0.f, s2 = 0.f, s3 = 0.f;
                const float4* kr = (const float4*)&Ks[kk * 64];
                #pragma unroll
                for (int d4 = 0; d4 < 16; d4++) {
                    float4 kv = kr[d4];
                    s0 = fmaf(qreg[d4*4+0], kv.x, s0);
                    s1 = fmaf(qreg[d4*4+1], kv.y, s1);
                    s2 = fmaf(qreg[d4*4+2], kv.z, s2);
                    s3 = fmaf(qreg[d4*4+3], kv.w, s3);
                }
                s = ((s0 + s1) + (s2 + s3)) * 0.125f;
            }
            Sc[tid * 65 + kk] = s;
            tmax = fmaxf(tmax, s);
        }
        if (tmax > -1e29f) {
            float nm = fmaxf(m, tmax);
            float scl = fexp(m - nm);
            l *= scl;
            #pragma unroll
            for (int d = 0; d < 64; d++) acc[d] *= scl;
            #pragma unroll 1
            for (int kk = 0; kk < 64; ++kk) {
                float p = fexp(Sc[tid * 65 + kk] - nm);
                l += p;
                const float4* vr = (const float4*)&Vs[kk * 64];
                #pragma unroll
                for (int d4 = 0; d4 < 16; d4++) {
                    float4 vv = vr[d4];
                    acc[d4*4+0] = fmaf(p, vv.x, acc[d4*4+0]);
                    acc[d4*4+1] = fmaf(p, vv.y, acc[d4*4+1]);
                    acc[d4*4+2] = fmaf(p, vv.z, acc[d4*4+2]);
                    acc[d4*4+3] = fmaf(p, vv.w, acc[d4*4+3]);
                }
            }
            m = nm;
        }
    }
    float inv = 1.f / l;
    __nv_bfloat162* oh = (__nv_bfloat162*)(g_cxh + (size_t)orig * Dm + h * HDim);
    __nv_bfloat162* ol = (__nv_bfloat162*)(g_cxl + (size_t)orig * Dm + h * HDim);
    #pragma unroll
    for (int d2 = 0; d2 < 32; d2++) {
        float v0 = acc[d2*2] * inv, v1 = acc[d2*2+1] * inv;
        __nv_bfloat16 h0 = __float2bfloat16(v0), h1 = __float2bfloat16(v1);
        __nv_bfloat162 H; H.x = h0; H.y = h1;
        oh[d2] = H;
        __nv_bfloat162 L;
        L.x = __float2bfloat16(v0 - __bfloat162float(h0));
        L.y = __float2bfloat16(v1 - __bfloat162float(h1));
        ol[d2] = L;
    }
}

// ---------------- host launcher ----------------------------------------------
#define SYM(p, s) do { void* _t; cudaGetSymbolAddress(&_t, s); p = (decltype(p))_t; } while (0)

extern "C" void kernel_launch(void* const* d_in, const int* in_sizes, int n_in,
                              void* d_out, int out_size) {
    const float* x      = (const float*)d_in[0];
    const float* attn_w = (const float*)d_in[1];
    const float* ffn_w  = (const float*)d_in[2];
    const float* Wq     = (const float*)d_in[3];
    const float* Wk     = (const float*)d_in[4];
    const float* Wv     = (const float*)d_in[5];
    const float* Wo     = (const float*)d_in[6];
    const float* Wr     = (const float*)d_in[7];
    const float* w1     = (const float*)d_in[8];
    const float* w2     = (const float*)d_in[9];
    const float* w3     = (const float*)d_in[10];
    float* out = (float*)d_out;

    float *p_qkvr, *p_x2;
    SYM(p_qkvr, g_qkvr); SYM(p_x2, g_x2);
    __nv_bfloat16 *p_hh, *p_hl, *p_cxh, *p_cxl, *p_s1h, *p_s1l;
    SYM(p_hh, g_hh); SYM(p_hl, g_hl); SYM(p_cxh, g_cxh); SYM(p_cxl, g_cxl);
    SYM(p_s1h, g_s1h); SYM(p_s1l, g_s1l);
    __nv_bfloat16 *wAh, *wAl, *woh, *wol, *w12h, *w12l, *w3h, *w3l;
    SYM(wAh, g_wAh); SYM(wAl, g_wAl); SYM(woh, g_woh); SYM(wol, g_wol);
    SYM(w12h, g_w12h); SYM(w12l, g_w12l); SYM(w3h, g_w3h); SYM(w3l, g_w3l);

    cudaFuncSetAttribute(attn_k, cudaFuncAttributeMaxDynamicSharedMemorySize, ATTN_SMEM);
    cudaFuncSetAttribute(gemm_hmma, cudaFuncAttributeMaxDynamicSharedMemorySize, GH_SMEM);

    dim3 tb(32, 8);
    // [0..3] A-side weight prep (router pad folded into wsplit via Nvalid guard)
    wsplit_k<<<dim3(Dm/32, Dm/32), tb>>>(Wq, wAh,           wAl,           Dm, Dm, 0, Dm);
    wsplit_k<<<dim3(Dm/32, Dm/32), tb>>>(Wk, wAh + 1024*Dm, wAl + 1024*Dm, Dm, Dm, 0, Dm);
    wsplit_k<<<dim3(Dm/32, Dm/32), tb>>>(Wv, wAh + 2048*Dm, wAl + 2048*Dm, Dm, Dm, 0, Dm);
    wsplit_k<<<dim3(4,     Dm/32), tb>>>(Wr, wAh + 3072*Dm, wAl + 3072*Dm, Dm, 64, 0, 64);

    // [4] h = rmsnorm(x) -> bf16 split
    rmsnorm_k<<<TOK, 256>>>(x, attn_w, p_hh, p_hl);

    // [5] fused q|k|v|router GEMM  (ncu -s 5 -c 1 lands here)
    gemm_hmma<<<dim3(NQKV/128, TOK/256), 512, GH_SMEM>>>(
        p_hh, p_hl, wAh, wAl, nullptr, p_qkvr, TOK, NQKV, NQKV, Dm,
        nullptr, nullptr, 0);

    // node/pos + partition & rope ; attention
    node_pos_k<<<32, 256>>>();
    permute_k<<<TOK * Hh / 4, 128>>>();
    attn_k<<<dim3(Ss / 128, 2 * Hh), 128, ATTN_SMEM>>>();

    // Wo prep + x2 = x + ctx @ Wo
    wsplit_k<<<dim3(Dm/32, Dm/32), tb>>>(Wo, woh, wol, Dm, Dm, 0, Dm);
    gemm_hmma<<<dim3(Dm/128, TOK/256), 512, GH_SMEM>>>(
        p_cxh, p_cxl, woh, wol, x, p_x2, TOK, Dm, Dm, Dm, nullptr, nullptr, 0);

    // h2 = rmsnorm(x2)
    rmsnorm_k<<<TOK, 256>>>(p_x2, ffn_w, p_hh, p_hl);

    // w1|w2 prep + fused GEMM with SwiGLU epilogue -> s1 (bf16 split)
    wsplit_k<<<dim3(Ff/32, Dm/32), tb>>>(w1, w12h, w12l, Dm, Ff, 1, Ff);
    wsplit_k<<<dim3(Ff/32, Dm/32), tb>>>(w2, w12h, w12l, Dm, Ff, 2, Ff);
    gemm_hmma<<<dim3(2*Ff/128, TOK/256), 512, GH_SMEM>>>(
        p_hh, p_hl, w12h, w12l, nullptr, nullptr, TOK, 2*Ff, 0, Dm,
        p_s1h, p_s1l, 1);

    // w3 prep + out = x2 + s1 @ w3
    wsplit_k<<<dim3(Dm/32, Ff/32), tb>>>(w3, w3h, w3l, Ff, Dm, 0, Dm);
    gemm_hmma<<<dim3(Dm/128, TOK/256), 512, GH_SMEM>>>(
        p_s1h, p_s1l, w3h, w3l, p_x2, out, TOK, Dm, Dm, Ff, nullptr, nullptr, 0);
}

// round 10
// speedup vs baseline: 2.7436x; 1.0485x over previous
#include <cuda_runtime.h>
#include <cuda_bf16.h>
#include <math.h>
#include <math_constants.h>
#include <stdint.h>

#define TOK 4096   // B*S
#define Dm  1024
#define Hh  16
#define HDim 64
#define Ff  4096
#define Ss  2048
#define NQKV 3200  // q(1024) k(1024) v(1024) router(64) pad(64)

// ---------------- fp32 scratch ----------------------------------------------
__device__ float g_qkvr[TOK*NQKV];
__device__ float g_x2 [TOK*Dm];
__device__ int   g_node[TOK*Hh];
__device__ float g_pos [TOK*Hh];
__device__ int   g_start [32*4];
__device__ int   g_qstart[32*Ss];
__device__ int   g_orig  [32*Ss];
__device__ float g_qp[32*Ss*HDim];
__device__ float g_kp[32*Ss*HDim];
__device__ float g_vp[32*Ss*HDim];

// ---------------- bf16 split activations ------------------------------------
__device__ __nv_bfloat16 g_hh [TOK*Dm], g_hl [TOK*Dm];
__device__ __nv_bfloat16 g_cxh[TOK*Dm], g_cxl[TOK*Dm];
__device__ __nv_bfloat16 g_s1h[TOK*Ff], g_s1l[TOK*Ff];

// ---------------- bf16 split transposed weights [N,K] -----------------------
__device__ __nv_bfloat16 g_wAh[NQKV*Dm], g_wAl[NQKV*Dm];    // Wq|Wk|Wv|Wr|0
__device__ __nv_bfloat16 g_woh[Dm*Dm],   g_wol[Dm*Dm];
__device__ __nv_bfloat16 g_w12h[2*Ff*Dm], g_w12l[2*Ff*Dm];  // w1/w2 interleaved
__device__ __nv_bfloat16 g_w3h[Dm*Ff],   g_w3l[Dm*Ff];

// ---------------- helpers -----------------------------------------------------
__device__ __forceinline__ uint32_t s2u(const void* p) {
    uint32_t a;
    asm("{ .reg .u64 t; cvta.to.shared.u64 t, %1; cvt.u32.u64 %0, t; }" : "=r"(a) : "l"(p));
    return a;
}

#define LDSM4(r, addr) \
    asm volatile("ldmatrix.sync.aligned.m8n8.x4.shared.b16 {%0,%1,%2,%3}, [%4];" \
        : "=r"((r)[0]), "=r"((r)[1]), "=r"((r)[2]), "=r"((r)[3]) : "r"(addr))

#define MMA(d, a, b) \
    asm volatile("mma.sync.aligned.m16n8k16.row.col.f32.bf16.bf16.f32 " \
        "{%0,%1,%2,%3}, {%4,%5,%6,%7}, {%8,%9}, {%0,%1,%2,%3};" \
        : "+f"((d)[0]), "+f"((d)[1]), "+f"((d)[2]), "+f"((d)[3]) \
        : "r"((a)[0]), "r"((a)[1]), "r"((a)[2]), "r"((a)[3]), "r"((b)[0]), "r"((b)[1]))

#define CPASYNC(dst, src) \
    asm volatile("cp.async.cg.shared.global [%0], [%1], 16;" :: "r"(dst), "l"(src))

// ---------------- fast exp (FMA pipe only) ----------------------------------
__device__ __forceinline__ float fexp(float x) {
    x = fminf(fmaxf(x, -87.0f), 88.0f);
    float y = x * 1.4426950408889634f;
    float n = rintf(y);
    float f = y - n;
    float p = 1.3333558146e-3f;
    p = fmaf(p, f, 9.6181291076e-3f);
    p = fmaf(p, f, 5.5504108665e-2f);
    p = fmaf(p, f, 2.4022650696e-1f);
    p = fmaf(p, f, 6.9314718056e-1f);
    p = fmaf(p, f, 1.0f);
    return p * __int_as_float(((int)n + 127) << 23);
}

// ---------------- HMMA split-bf16 GEMM, 2-stage, 2 CTAs/SM (round-6 winner) --
#define BUF_BYTES 40960
#define GH_SMEM   (2 * BUF_BYTES)

__global__ __launch_bounds__(256, 2)
void gemm_hmma(const __nv_bfloat16* __restrict__ Ah, const __nv_bfloat16* __restrict__ Al,
               const __nv_bfloat16* __restrict__ Bh, const __nv_bfloat16* __restrict__ Bl,
               const float* __restrict__ R, float* __restrict__ C,
               int M, int Nc, int ldc, int K,
               __nv_bfloat16* __restrict__ Oh, __nv_bfloat16* __restrict__ Ol, int swiglu) {
    extern __shared__ char smraw[];
    const int tid  = threadIdx.x;
    const int lane = tid & 31, wid = tid >> 5;
    const int m0 = blockIdx.y * 128, n0 = blockIdx.x * 128;
    const int warp_m = (wid >> 2) * 64, warp_n = (wid & 3) * 32;
    const int nc = K >> 5;
    const uint32_t sb = s2u(smraw);

    const char* gA  = (const char*)Ah + (size_t)m0 * K * 2;
    const char* gAl = (const char*)Al + (size_t)m0 * K * 2;
    const char* gB  = (const char*)Bh + (size_t)n0 * K * 2;
    const char* gBl = (const char*)Bl + (size_t)n0 * K * 2;

    int lr0 = tid >> 2,          lc0 = (tid & 3) * 16;
    int lr1 = (tid + 256) >> 2,  lc1 = lc0;

    #define ISSUE(buf, kc) do { \
        uint32_t db = sb + (buf) * BUF_BYTES; \
        size_t ko = (size_t)(kc) * 64; \
        uint32_t so0 = lr0 * 80 + lc0, so1 = lr1 * 80 + lc1; \
        size_t go0 = (size_t)lr0 * (K * 2) + ko + lc0; \
        size_t go1 = (size_t)lr1 * (K * 2) + ko + lc1; \
        CPASYNC(db + so0,         gA  + go0); CPASYNC(db + so1,         gA  + go1); \
        CPASYNC(db + 10240 + so0, gAl + go0); CPASYNC(db + 10240 + so1, gAl + go1); \
        CPASYNC(db + 20480 + so0, gB  + go0); CPASYNC(db + 20480 + so1, gB  + go1); \
        CPASYNC(db + 30720 + so0, gBl + go0); CPASYNC(db + 30720 + so1, gBl + go1); \
        asm volatile("cp.async.commit_group;"); \
    } while (0)

    ISSUE(0, 0);
    ISSUE(1, 1);

    float acc[4][4][4];
    #pragma unroll
    for (int i = 0; i < 4; i++)
        #pragma unroll
        for (int j = 0; j < 4; j++)
            #pragma unroll
            for (int q = 0; q < 4; q++) acc[i][j][q] = 0.f;

    const int a_row = (lane & 7) + ((lane >> 3) & 1) * 8;
    const int a_cb  = (lane >> 4) * 16;
    const int b_row = (lane & 7) + (lane >> 4) * 8;
    const int b_cb  = ((lane >> 3) & 1) * 16;
    const uint32_t aoff = (warp_m + a_row) * 80 + a_cb;
    const uint32_t boff = 20480 + (warp_n + b_row) * 80 + b_cb;

    #pragma unroll 1
    for (int kc = 0; kc < nc; kc++) {
        if (kc + 1 < nc) asm volatile("cp.async.wait_group 1;");
        else             asm volatile("cp.async.wait_group 0;");
        __syncthreads();
        uint32_t db = sb + (kc & 1) * BUF_BYTES;
        #pragma unroll
        for (int ks = 0; ks < 2; ks++) {
            uint32_t ah[4][4], bh[4][2], bl[4][2];
            #pragma unroll
            for (int mt = 0; mt < 4; mt++)
                LDSM4(ah[mt], db + aoff + mt * (16 * 80) + ks * 32);
            #pragma unroll
            for (int p = 0; p < 2; p++) {
                uint32_t bd = db + boff + p * (16 * 80) + ks * 32;
                LDSM4(&bh[2 * p][0], bd);
                LDSM4(&bl[2 * p][0], bd + 10240);
            }
            #pragma unroll
            for (int mt = 0; mt < 4; mt++)
                #pragma unroll
                for (int nt = 0; nt < 4; nt++) MMA(acc[mt][nt], ah[mt], bh[nt]);
            #pragma unroll
            for (int mt = 0; mt < 4; mt++)
                #pragma unroll
                for (int nt = 0; nt < 4; nt++) MMA(acc[mt][nt], ah[mt], bl[nt]);
            uint32_t al[4][4];
            #pragma unroll
            for (int mt = 0; mt < 4; mt++)
                LDSM4(al[mt], db + aoff + mt * (16 * 80) + ks * 32 + 10240);
            #pragma unroll
            for (int mt = 0; mt < 4; mt++)
                #pragma unroll
                for (int nt = 0; nt < 4; nt++) MMA(acc[mt][nt], al[mt], bh[nt]);
        }
        __syncthreads();
        if (kc + 2 < nc) ISSUE(kc & 1, kc + 2);
    }
    #undef ISSUE

    const int g  = lane >> 2;
    const int cc = (lane & 3) * 2;

    if (swiglu) {
        float* sm2 = (float*)smraw;          // [128][68] fp32 staging for a2
        if ((wid & 3) >= 2) {
            #pragma unroll
            for (int mt = 0; mt < 4; mt++) {
                int row0 = warp_m + mt * 16 + g;
                #pragma unroll
                for (int nt = 0; nt < 4; nt++) {
                    int c = warp_n - 64 + nt * 8 + cc;
                    sm2[row0 * 68 + c]           = acc[mt][nt][0];
                    sm2[row0 * 68 + c + 1]       = acc[mt][nt][1];
                    sm2[(row0 + 8) * 68 + c]     = acc[mt][nt][2];
                    sm2[(row0 + 8) * 68 + c + 1] = acc[mt][nt][3];
                }
            }
        }
        __syncthreads();
        if ((wid & 3) < 2) {
            size_t colbase = (size_t)blockIdx.x * 64;
            #pragma unroll
            for (int mt = 0; mt < 4; mt++) {
                #pragma unroll
                for (int rr = 0; rr < 2; rr++) {
                    int row = warp_m + mt * 16 + g + rr * 8;
                    size_t orow = (size_t)(m0 + row) * Ff + colbase;
                    #pragma unroll
                    for (int nt = 0; nt < 4; nt++) {
                        int c = warp_n + nt * 8 + cc;
                        float a1a = acc[mt][nt][rr * 2], a1b = acc[mt][nt][rr * 2 + 1];
                        float a2a = sm2[row * 68 + c], a2b = sm2[row * 68 + c + 1];
                        float r0 = a1a / (1.f + fexp(-a1a)) * a2a;
                        float r1 = a1b / (1.f + fexp(-a1b)) * a2b;
                        __nv_bfloat16 h0 = __float2bfloat16(r0), h1 = __float2bfloat16(r1);
                        __nv_bfloat162 H; H.x = h0; H.y = h1;
                        *(__nv_bfloat162*)(Oh + orow + c) = H;
                        __nv_bfloat162 L;
                        L.x = __float2bfloat16(r0 - __bfloat162float(h0));
                        L.y = __float2bfloat16(r1 - __bfloat162float(h1));
                        *(__nv_bfloat162*)(Ol + orow + c) = L;
                    }
                }
            }
        }
        return;
    }

    #pragma unroll
    for (int mt = 0; mt < 4; mt++) {
        int row0 = m0 + warp_m + mt * 16 + g;
        #pragma unroll
        for (int nt = 0; nt < 4; nt++) {
            int col = n0 + warp_n + nt * 8 + cc;
            if (col < Nc) {
                float2 v0 = make_float2(acc[mt][nt][0], acc[mt][nt][1]);
                float2 v1 = make_float2(acc[mt][nt][2], acc[mt][nt][3]);
                if (R) {
                    float2 r0 = *(const float2*)(R + (size_t)row0 * ldc + col);
                    float2 r1 = *(const float2*)(R + (size_t)(row0 + 8) * ldc + col);
                    v0.x += r0.x; v0.y += r0.y; v1.x += r1.x; v1.y += r1.y;
                }
                *(float2*)(C + (size_t)row0 * ldc + col)       = v0;
                *(float2*)(C + (size_t)(row0 + 8) * ldc + col) = v1;
            }
        }
    }
}

// ---------------- weight transpose + bf16 split ------------------------------
__global__ void wsplit_k(const float* __restrict__ W, __nv_bfloat16* __restrict__ Th,
                         __nv_bfloat16* __restrict__ Tl, int Kd, int Nd, int mode,
                         int Nvalid) {
    __shared__ float t[32][33];
    int n0 = blockIdx.x * 32, k0 = blockIdx.y * 32;
    int tx = threadIdx.x, ty = threadIdx.y;
    #pragma unroll
    for (int i = 0; i < 4; i++)
        t[ty + i * 8][tx] = (n0 + tx < Nvalid)
            ? W[(size_t)(k0 + ty + i * 8) * Nd + n0 + tx] : 0.f;
    __syncthreads();
    #pragma unroll
    for (int i = 0; i < 4; i++) {
        int r = ty + i * 8;
        int n = n0 + r;
        size_t orow = (mode == 0) ? (size_t)n
                    : (size_t)((n >> 6) * 128 + (n & 63) + ((mode == 2) ? 64 : 0));
        float v = t[tx][r];
        __nv_bfloat16 hb = __float2bfloat16(v);
        size_t o = orow * Kd + k0 + tx;
        Th[o] = hb;
        Tl[o] = __float2bfloat16(v - __bfloat162float(hb));
    }
}

// ---------------- rmsnorm -> bf16 split --------------------------------------
__global__ void rmsnorm_k(const float* __restrict__ x, const float* __restrict__ w,
                          __nv_bfloat16* __restrict__ oh, __nv_bfloat16* __restrict__ ol) {
    int row = blockIdx.x;
    const float4* xr = (const float4*)(x + (size_t)row * Dm);
    float4 v = xr[threadIdx.x];
    float ss = v.x*v.x + v.y*v.y + v.z*v.z + v.w*v.w;
    #pragma unroll
    for (int o = 16; o; o >>= 1) ss += __shfl_xor_sync(0xffffffffu, ss, o);
    __shared__ float sws[8];
    int lane = threadIdx.x & 31, wid = threadIdx.x >> 5;
    if (lane == 0) sws[wid] = ss;
    __syncthreads();
    if (threadIdx.x == 0) {
        float t = 0.f;
        #pragma unroll
        for (int i = 0; i < 8; i++) t += sws[i];
        sws[0] = rsqrtf(t * (1.0f / Dm) + 1e-6f);
    }
    __syncthreads();
    float inv = sws[0];
    float4 wv = ((const float4*)w)[threadIdx.x];
    float4 o4;
    o4.x = v.x * inv * wv.x; o4.y = v.y * inv * wv.y;
    o4.z = v.z * inv * wv.z; o4.w = v.w * inv * wv.w;
    __nv_bfloat16 h0 = __float2bfloat16(o4.x), h1 = __float2bfloat16(o4.y);
    __nv_bfloat16 h2 = __float2bfloat16(o4.z), h3 = __float2bfloat16(o4.w);
    __nv_bfloat162 H0; H0.x = h0; H0.y = h1;
    __nv_bfloat162 H1; H1.x = h2; H1.y = h3;
    __nv_bfloat162* ph = (__nv_bfloat162*)(oh + (size_t)row * Dm);
    ph[threadIdx.x * 2]     = H0;
    ph[threadIdx.x * 2 + 1] = H1;
    __nv_bfloat162 L0, L1;
    L0.x = __float2bfloat16(o4.x - __bfloat162float(h0));
    L0.y = __float2bfloat16(o4.y - __bfloat162float(h1));
    L1.x = __float2bfloat16(o4.z - __bfloat162float(h2));
    L1.y = __float2bfloat16(o4.w - __bfloat162float(h3));
    __nv_bfloat162* pl = (__nv_bfloat162*)(ol + (size_t)row * Dm);
    pl[threadIdx.x * 2]     = L0;
    pl[threadIdx.x * 2 + 1] = L1;
}

// ---------------- node/pos + partition starts --------------------------------
__global__ void node_pos_k() {
    int bh = blockIdx.x;
    int b = bh >> 4, h = bh & 15;
    int t = threadIdx.x;
    __shared__ int cnts[256][4];
    __shared__ int base[256][4];
    int myn[8], posl[8];
    int local[4] = {0, 0, 0, 0};
    #pragma unroll
    for (int j = 0; j < 8; j++) {
        int s = t * 8 + j;
        int tok = b * Ss + s;
        const float* lp = g_qkvr + (size_t)tok * NQKV + 3072 + h * 4;
        float l0 = lp[0], l1 = lp[1], l2 = lp[2], l3 = lp[3];
        int n = 0; float bv = l0;
        if (l1 > bv) { bv = l1; n = 1; }
        if (l2 > bv) { bv = l2; n = 2; }
        if (l3 > bv) { bv = l3; n = 3; }
        myn[j] = n;
        posl[j] = local[n];
        local[n]++;
    }
    cnts[t][0] = local[0]; cnts[t][1] = local[1];
    cnts[t][2] = local[2]; cnts[t][3] = local[3];
    __syncthreads();
    if (t == 0) {
        int run[4] = {0, 0, 0, 0};
        for (int i = 0; i < 256; i++)
            #pragma unroll
            for (int v = 0; v < 4; v++) { base[i][v] = run[v]; run[v] += cnts[i][v]; }
        int st = 0;
        #pragma unroll
        for (int v = 0; v < 4; v++) { g_start[bh * 4 + v] = st; st += run[v]; }
    }
    __syncthreads();
    #pragma unroll
    for (int j = 0; j < 8; j++) {
        int s = t * 8 + j;
        int tok = b * Ss + s;
        int n = myn[j];
        g_node[tok * Hh + h] = n;
        g_pos[tok * Hh + h] = (float)(base[t][n] + posl[j]);
    }
}

// ---------------- permute (node partition) + RoPE ----------------------------
__global__ void permute_k() {
    int inst = blockIdx.x * 4 + (threadIdx.x >> 5);   // tok*16 + h
    int lane = threadIdx.x & 31;
    int tok = inst >> 4, h = inst & 15;
    int b = tok >> 11;
    int bh = b * 16 + h;
    int n = g_node[tok * Hh + h];
    float pos = g_pos[tok * Hh + h];
    int startn = g_start[bh * 4 + n];
    int slot = startn + (int)pos;
    const float* src = g_qkvr + (size_t)tok * NQKV;
    float invf = exp2f(-(float)lane * (13.287712379549449f / 32.0f));
    float ang = pos * invf;
    float s, c;
    sincosf(ang, &s, &c);
    size_t drow = ((size_t)bh * Ss + slot) * HDim;
    float q1 = src[h * 64 + lane], q2 = src[h * 64 + lane + 32];
    g_qp[drow + lane]      = q1 * c - q2 * s;
    g_qp[drow + lane + 32] = q2 * c + q1 * s;
    float k1 = src[1024 + h * 64 + lane], k2 = src[1024 + h * 64 + lane + 32];
    g_kp[drow + lane]      = k1 * c - k2 * s;
    g_kp[drow + lane + 32] = k2 * c + k1 * s;
    g_vp[drow + lane]      = src[2048 + h * 64 + lane];
    g_vp[drow + lane + 32] = src[2048 + h * 64 + lane + 32];
    if (lane == 0) {
        g_qstart[bh * Ss + slot] = startn;
        g_orig  [bh * Ss + slot] = tok;
    }
}

// ---------------- attention: per-partition causal flash, bounded loops -------
#define ATTN_SMEM ((4096 + 4096 + 128 * 65) * 4)
__global__ __launch_bounds__(128)
void attn_k() {
    int bh = blockIdx.y;
    int h = bh & 15;
    int q0 = blockIdx.x * 128;
    int tid = threadIdx.x;
    int j = q0 + tid;
    size_t base = (size_t)bh * Ss;
    extern __shared__ float sm[];
    float* Ks = sm;
    float* Vs = sm + 4096;
    float* Sc = sm + 8192;

    float qreg[64];
    const float4* qp = (const float4*)(g_qp + (base + j) * HDim);
    #pragma unroll
    for (int d4 = 0; d4 < 16; d4++) {
        float4 v = qp[d4];
        qreg[d4*4+0] = v.x; qreg[d4*4+1] = v.y; qreg[d4*4+2] = v.z; qreg[d4*4+3] = v.w;
    }
    int startq = g_qstart[base + j];
    int orig   = g_orig[base + j];
    int kt0 = g_qstart[base + q0] >> 6;
    int ktE = (q0 >> 6) + 2;

    float m = -CUDART_INF_F, l = 0.f;
    float acc[64];
    #pragma unroll
    for (int d = 0; d < 64; d++) acc[d] = 0.f;

    for (int kt = kt0; kt < ktE; ++kt) {
        int kb = kt * 64;
        __syncthreads();
        for (int e = tid; e < 1024; e += 128) {
            int r = e >> 4, c = (e & 15) * 4;
            size_t srow = (base + kb + r) * HDim;
            *(float4*)&Ks[r * 64 + c] = *(const float4*)(g_kp + srow + c);
            *(float4*)&Vs[r * 64 + c] = *(const float4*)(g_vp + srow + c);
        }
        __syncthreads();

        // per-thread live range within this tile
        int kk0 = startq - kb; kk0 = kk0 > 0 ? kk0 : 0;
        int kk1 = j - kb + 1;  kk1 = kk1 < 64 ? kk1 : 64;
        if (kk1 <= kk0) continue;

        float tmax = -CUDART_INF_F;
        #pragma unroll 1
        for (int kk = kk0; kk < kk1; ++kk) {
            float s0 = 0.f, s1 = 0.f, s2 = 0.f, s3 = 0.f;
            const float4* kr = (const float4*)&Ks[kk * 64];
            #pragma unroll
            for (int d4 = 0; d4 < 16; d4++) {
                float4 kv = kr[d4];
                s0 = fmaf(qreg[d4*4+0], kv.x, s0);
                s1 = fmaf(qreg[d4*4+1], kv.y, s1);
                s2 = fmaf(qreg[d4*4+2], kv.z, s2);
                s3 = fmaf(qreg[d4*4+3], kv.w, s3);
            }
            float s = ((s0 + s1) + (s2 + s3)) * 0.125f;
            Sc[tid * 65 + kk] = s;
            tmax = fmaxf(tmax, s);
        }
        float nm = fmaxf(m, tmax);
        float scl = fexp(m - nm);
        l *= scl;
        #pragma unroll
        for (int d = 0; d < 64; d++) acc[d] *= scl;
        #pragma unroll 1
        for (int kk = kk0; kk < kk1; ++kk) {
            float p = fexp(Sc[tid * 65 + kk] - nm);
            l += p;
            const float4* vr = (const float4*)&Vs[kk * 64];
            #pragma unroll
            for (int d4 = 0; d4 < 16; d4++) {
                float4 vv = vr[d4];
                acc[d4*4+0] = fmaf(p, vv.x, acc[d4*4+0]);
                acc[d4*4+1] = fmaf(p, vv.y, acc[d4*4+1]);
                acc[d4*4+2] = fmaf(p, vv.z, acc[d4*4+2]);
                acc[d4*4+3] = fmaf(p, vv.w, acc[d4*4+3]);
            }
        }
        m = nm;
    }
    float inv = 1.f / l;
    __nv_bfloat162* oh = (__nv_bfloat162*)(g_cxh + (size_t)orig * Dm + h * HDim);
    __nv_bfloat162* ol = (__nv_bfloat162*)(g_cxl + (size_t)orig * Dm + h * HDim);
    #pragma unroll
    for (int d2 = 0; d2 < 32; d2++) {
        float v0 = acc[d2*2] * inv, v1 = acc[d2*2+1] * inv;
        __nv_bfloat16 h0 = __float2bfloat16(v0), h1 = __float2bfloat16(v1);
        __nv_bfloat162 H; H.x = h0; H.y = h1;
        oh[d2] = H;
        __nv_bfloat162 L;
        L.x = __float2bfloat16(v0 - __bfloat162float(h0));
        L.y = __float2bfloat16(v1 - __bfloat162float(h1));
        ol[d2] = L;
    }
}

// ---------------- host launcher ----------------------------------------------
#define SYM(p, s) do { void* _t; cudaGetSymbolAddress(&_t, s); p = (decltype(p))_t; } while (0)

extern "C" void kernel_launch(void* const* d_in, const int* in_sizes, int n_in,
                              void* d_out, int out_size) {
    const float* x      = (const float*)d_in[0];
    const float* attn_w = (const float*)d_in[1];
    const float* ffn_w  = (const float*)d_in[2];
    const float* Wq     = (const float*)d_in[3];
    const float* Wk     = (const float*)d_in[4];
    const float* Wv     = (const float*)d_in[5];
    const float* Wo     = (const float*)d_in[6];
    const float* Wr     = (const float*)d_in[7];
    const float* w1     = (const float*)d_in[8];
    const float* w2     = (const float*)d_in[9];
    const float* w3     = (const float*)d_in[10];
    float* out = (float*)d_out;

    float *p_qkvr, *p_x2;
    SYM(p_qkvr, g_qkvr); SYM(p_x2, g_x2);
    __nv_bfloat16 *p_hh, *p_hl, *p_cxh, *p_cxl, *p_s1h, *p_s1l;
    SYM(p_hh, g_hh); SYM(p_hl, g_hl); SYM(p_cxh, g_cxh); SYM(p_cxl, g_cxl);
    SYM(p_s1h, g_s1h); SYM(p_s1l, g_s1l);
    __nv_bfloat16 *wAh, *wAl, *woh, *wol, *w12h, *w12l, *w3h, *w3l;
    SYM(wAh, g_wAh); SYM(wAl, g_wAl); SYM(woh, g_woh); SYM(wol, g_wol);
    SYM(w12h, g_w12h); SYM(w12l, g_w12l); SYM(w3h, g_w3h); SYM(w3l, g_w3l);

    cudaFuncSetAttribute(attn_k, cudaFuncAttributeMaxDynamicSharedMemorySize, ATTN_SMEM);
    cudaFuncSetAttribute(gemm_hmma, cudaFuncAttributeMaxDynamicSharedMemorySize, GH_SMEM);

    dim3 tb(32, 8);
    wsplit_k<<<dim3(Dm/32, Dm/32), tb>>>(Wq, wAh,           wAl,           Dm, Dm, 0, Dm);
    wsplit_k<<<dim3(Dm/32, Dm/32), tb>>>(Wk, wAh + 1024*Dm, wAl + 1024*Dm, Dm, Dm, 0, Dm);
    wsplit_k<<<dim3(Dm/32, Dm/32), tb>>>(Wv, wAh + 2048*Dm, wAl + 2048*Dm, Dm, Dm, 0, Dm);
    wsplit_k<<<dim3(4,     Dm/32), tb>>>(Wr, wAh + 3072*Dm, wAl + 3072*Dm, Dm, 64, 0, 64);

    // h = rmsnorm(x) -> bf16 split
    rmsnorm_k<<<TOK, 256>>>(x, attn_w, p_hh, p_hl);

    // fused q|k|v|router GEMM
    gemm_hmma<<<dim3(NQKV/128, TOK/128), 256, GH_SMEM>>>(
        p_hh, p_hl, wAh, wAl, nullptr, p_qkvr, TOK, NQKV, NQKV, Dm,
        nullptr, nullptr, 0);

    // node/pos + partition & rope ; attention
    node_pos_k<<<32, 256>>>();
    permute_k<<<TOK * Hh / 4, 128>>>();
    attn_k<<<dim3(Ss / 128, 2 * Hh), 128, ATTN_SMEM>>>();

    // Wo prep + x2 = x + ctx @ Wo
    wsplit_k<<<dim3(Dm/32, Dm/32), tb>>>(Wo, woh, wol, Dm, Dm, 0, Dm);
    gemm_hmma<<<dim3(Dm/128, TOK/128), 256, GH_SMEM>>>(
        p_cxh, p_cxl, woh, wol, x, p_x2, TOK, Dm, Dm, Dm, nullptr, nullptr, 0);

    // h2 = rmsnorm(x2)
    rmsnorm_k<<<TOK, 256>>>(p_x2, ffn_w, p_hh, p_hl);

    // w1|w2 prep + fused GEMM with SwiGLU epilogue -> s1 (bf16 split)
    wsplit_k<<<dim3(Ff/32, Dm/32), tb>>>(w1, w12h, w12l, Dm, Ff, 1, Ff);
    wsplit_k<<<dim3(Ff/32, Dm/32), tb>>>(w2, w12h, w12l, Dm, Ff, 2, Ff);
    gemm_hmma<<<dim3(2*Ff/128, TOK/128), 256, GH_SMEM>>>(
        p_hh, p_hl, w12h, w12l, nullptr, nullptr, TOK, 2*Ff, 0, Dm,
        p_s1h, p_s1l, 1);

    // w3 prep + out = x2 + s1 @ w3
    wsplit_k<<<dim3(Dm/32, Ff/32), tb>>>(w3, w3h, w3l, Ff, Dm, 0, Dm);
    gemm_hmma<<<dim3(Dm/128, TOK/128), 256, GH_SMEM>>>(
        p_s1h, p_s1l, w3h, w3l, p_x2, out, TOK, Dm, Dm, Ff, nullptr, nullptr, 0);
}

// round 11
// speedup vs baseline: 2.7786x; 1.0128x over previous
#include <cuda_runtime.h>
#include <cuda_bf16.h>
#include <math.h>
#include <math_constants.h>
#include <stdint.h>

#define TOK 4096   // B*S
#define Dm  1024
#define Hh  16
#define HDim 64
#define Ff  4096
#define Ss  2048
#define NQKV 3200  // q(1024) k(1024) v(1024) router(64) pad(64)

// ---------------- fp32 scratch ----------------------------------------------
__device__ float g_qkvr[TOK*NQKV];
__device__ float g_x2 [TOK*Dm];
__device__ int   g_node[TOK*Hh];
__device__ float g_pos [TOK*Hh];
__device__ int   g_start [32*4];
__device__ int   g_qstart[32*Ss];
__device__ int   g_orig  [32*Ss];
__device__ float g_qp[32*Ss*HDim];
__device__ float g_kp[32*Ss*HDim];
__device__ float g_vp[32*Ss*HDim];

// ---------------- bf16 split activations ------------------------------------
__device__ __nv_bfloat16 g_hh [TOK*Dm], g_hl [TOK*Dm];
__device__ __nv_bfloat16 g_cxh[TOK*Dm], g_cxl[TOK*Dm];
__device__ __nv_bfloat16 g_s1h[TOK*Ff], g_s1l[TOK*Ff];

// ---------------- bf16 split transposed weights [N,K] -----------------------
__device__ __nv_bfloat16 g_wAh[NQKV*Dm], g_wAl[NQKV*Dm];    // Wq|Wk|Wv|Wr|0
__device__ __nv_bfloat16 g_woh[Dm*Dm],   g_wol[Dm*Dm];
__device__ __nv_bfloat16 g_w12h[2*Ff*Dm], g_w12l[2*Ff*Dm];  // w1/w2 interleaved
__device__ __nv_bfloat16 g_w3h[Dm*Ff],   g_w3l[Dm*Ff];

// ---------------- helpers -----------------------------------------------------
__device__ __forceinline__ uint32_t s2u(const void* p) {
    uint32_t a;
    asm("{ .reg .u64 t; cvta.to.shared.u64 t, %1; cvt.u32.u64 %0, t; }" : "=r"(a) : "l"(p));
    return a;
}

#define LDSM4(r, addr) \
    asm volatile("ldmatrix.sync.aligned.m8n8.x4.shared.b16 {%0,%1,%2,%3}, [%4];" \
        : "=r"((r)[0]), "=r"((r)[1]), "=r"((r)[2]), "=r"((r)[3]) : "r"(addr))

#define MMA(d, a, b) \
    asm volatile("mma.sync.aligned.m16n8k16.row.col.f32.bf16.bf16.f32 " \
        "{%0,%1,%2,%3}, {%4,%5,%6,%7}, {%8,%9}, {%0,%1,%2,%3};" \
        : "+f"((d)[0]), "+f"((d)[1]), "+f"((d)[2]), "+f"((d)[3]) \
        : "r"((a)[0]), "r"((a)[1]), "r"((a)[2]), "r"((a)[3]), "r"((b)[0]), "r"((b)[1]))

#define CPASYNC(dst, src) \
    asm volatile("cp.async.cg.shared.global [%0], [%1], 16;" :: "r"(dst), "l"(src))

// ---------------- fast exp (FMA pipe only) ----------------------------------
__device__ __forceinline__ float fexp(float x) {
    x = fminf(fmaxf(x, -87.0f), 88.0f);
    float y = x * 1.4426950408889634f;
    float n = rintf(y);
    float f = y - n;
    float p = 1.3333558146e-3f;
    p = fmaf(p, f, 9.6181291076e-3f);
    p = fmaf(p, f, 5.5504108665e-2f);
    p = fmaf(p, f, 2.4022650696e-1f);
    p = fmaf(p, f, 6.9314718056e-1f);
    p = fmaf(p, f, 1.0f);
    return p * __int_as_float(((int)n + 127) << 23);
}

// ---------------- HMMA split-bf16 GEMM, 2-stage, 2 CTAs/SM -------------------
#define BUF_BYTES 40960
#define GH_SMEM   (2 * BUF_BYTES)

__global__ __launch_bounds__(256, 2)
void gemm_hmma(const __nv_bfloat16* __restrict__ Ah, const __nv_bfloat16* __restrict__ Al,
               const __nv_bfloat16* __restrict__ Bh, const __nv_bfloat16* __restrict__ Bl,
               const float* __restrict__ R, float* __restrict__ C,
               int M, int Nc, int ldc, int K,
               __nv_bfloat16* __restrict__ Oh, __nv_bfloat16* __restrict__ Ol, int swiglu) {
    extern __shared__ char smraw[];
    const int tid  = threadIdx.x;
    const int lane = tid & 31, wid = tid >> 5;
    const int m0 = blockIdx.y * 128, n0 = blockIdx.x * 128;
    const int warp_m = (wid >> 2) * 64, warp_n = (wid & 3) * 32;
    const int nc = K >> 5;
    const uint32_t sb = s2u(smraw);

    const char* gA  = (const char*)Ah + (size_t)m0 * K * 2;
    const char* gAl = (const char*)Al + (size_t)m0 * K * 2;
    const char* gB  = (const char*)Bh + (size_t)n0 * K * 2;
    const char* gBl = (const char*)Bl + (size_t)n0 * K * 2;

    int lr0 = tid >> 2,          lc0 = (tid & 3) * 16;
    int lr1 = (tid + 256) >> 2,  lc1 = lc0;

    #define ISSUE(buf, kc) do { \
        uint32_t db = sb + (buf) * BUF_BYTES; \
        size_t ko = (size_t)(kc) * 64; \
        uint32_t so0 = lr0 * 80 + lc0, so1 = lr1 * 80 + lc1; \
        size_t go0 = (size_t)lr0 * (K * 2) + ko + lc0; \
        size_t go1 = (size_t)lr1 * (K * 2) + ko + lc1; \
        CPASYNC(db + so0,         gA  + go0); CPASYNC(db + so1,         gA  + go1); \
        CPASYNC(db + 10240 + so0, gAl + go0); CPASYNC(db + 10240 + so1, gAl + go1); \
        CPASYNC(db + 20480 + so0, gB  + go0); CPASYNC(db + 20480 + so1, gB  + go1); \
        CPASYNC(db + 30720 + so0, gBl + go0); CPASYNC(db + 30720 + so1, gBl + go1); \
        asm volatile("cp.async.commit_group;"); \
    } while (0)

    ISSUE(0, 0);
    ISSUE(1, 1);

    float acc[4][4][4];
    #pragma unroll
    for (int i = 0; i < 4; i++)
        #pragma unroll
        for (int j = 0; j < 4; j++)
            #pragma unroll
            for (int q = 0; q < 4; q++) acc[i][j][q] = 0.f;

    const int a_row = (lane & 7) + ((lane >> 3) & 1) * 8;
    const int a_cb  = (lane >> 4) * 16;
    const int b_row = (lane & 7) + (lane >> 4) * 8;
    const int b_cb  = ((lane >> 3) & 1) * 16;
    const uint32_t aoff = (warp_m + a_row) * 80 + a_cb;
    const uint32_t boff = 20480 + (warp_n + b_row) * 80 + b_cb;

    #pragma unroll 1
    for (int kc = 0; kc < nc; kc++) {
        if (kc + 1 < nc) asm volatile("cp.async.wait_group 1;");
        else             asm volatile("cp.async.wait_group 0;");
        __syncthreads();
        uint32_t db = sb + (kc & 1) * BUF_BYTES;
        #pragma unroll
        for (int ks = 0; ks < 2; ks++) {
            uint32_t ah[4][4], bh[4][2], bl[4][2];
            #pragma unroll
            for (int mt = 0; mt < 4; mt++)
                LDSM4(ah[mt], db + aoff + mt * (16 * 80) + ks * 32);
            #pragma unroll
            for (int p = 0; p < 2; p++) {
                uint32_t bd = db + boff + p * (16 * 80) + ks * 32;
                LDSM4(&bh[2 * p][0], bd);
                LDSM4(&bl[2 * p][0], bd + 10240);
            }
            #pragma unroll
            for (int mt = 0; mt < 4; mt++)
                #pragma unroll
                for (int nt = 0; nt < 4; nt++) MMA(acc[mt][nt], ah[mt], bh[nt]);
            #pragma unroll
            for (int mt = 0; mt < 4; mt++)
                #pragma unroll
                for (int nt = 0; nt < 4; nt++) MMA(acc[mt][nt], ah[mt], bl[nt]);
            uint32_t al[4][4];
            #pragma unroll
            for (int mt = 0; mt < 4; mt++)
                LDSM4(al[mt], db + aoff + mt * (16 * 80) + ks * 32 + 10240);
            #pragma unroll
            for (int mt = 0; mt < 4; mt++)
                #pragma unroll
                for (int nt = 0; nt < 4; nt++) MMA(acc[mt][nt], al[mt], bh[nt]);
        }
        __syncthreads();
        if (kc + 2 < nc) ISSUE(kc & 1, kc + 2);
    }
    #undef ISSUE

    const int g  = lane >> 2;
    const int cc = (lane & 3) * 2;

    if (swiglu) {
        float* sm2 = (float*)smraw;          // [128][68] fp32 staging for a2
        if ((wid & 3) >= 2) {
            #pragma unroll
            for (int mt = 0; mt < 4; mt++) {
                int row0 = warp_m + mt * 16 + g;
                #pragma unroll
                for (int nt = 0; nt < 4; nt++) {
                    int c = warp_n - 64 + nt * 8 + cc;
                    sm2[row0 * 68 + c]           = acc[mt][nt][0];
                    sm2[row0 * 68 + c + 1]       = acc[mt][nt][1];
                    sm2[(row0 + 8) * 68 + c]     = acc[mt][nt][2];
                    sm2[(row0 + 8) * 68 + c + 1] = acc[mt][nt][3];
                }
            }
        }
        __syncthreads();
        if ((wid & 3) < 2) {
            size_t colbase = (size_t)blockIdx.x * 64;
            #pragma unroll
            for (int mt = 0; mt < 4; mt++) {
                #pragma unroll
                for (int rr = 0; rr < 2; rr++) {
                    int row = warp_m + mt * 16 + g + rr * 8;
                    size_t orow = (size_t)(m0 + row) * Ff + colbase;
                    #pragma unroll
                    for (int nt = 0; nt < 4; nt++) {
                        int c = warp_n + nt * 8 + cc;
                        float a1a = acc[mt][nt][rr * 2], a1b = acc[mt][nt][rr * 2 + 1];
                        float a2a = sm2[row * 68 + c], a2b = sm2[row * 68 + c + 1];
                        float r0 = a1a / (1.f + fexp(-a1a)) * a2a;
                        float r1 = a1b / (1.f + fexp(-a1b)) * a2b;
                        __nv_bfloat16 h0 = __float2bfloat16(r0), h1 = __float2bfloat16(r1);
                        __nv_bfloat162 H; H.x = h0; H.y = h1;
                        *(__nv_bfloat162*)(Oh + orow + c) = H;
                        __nv_bfloat162 L;
                        L.x = __float2bfloat16(r0 - __bfloat162float(h0));
                        L.y = __float2bfloat16(r1 - __bfloat162float(h1));
                        *(__nv_bfloat162*)(Ol + orow + c) = L;
                    }
                }
            }
        }
        return;
    }

    #pragma unroll
    for (int mt = 0; mt < 4; mt++) {
        int row0 = m0 + warp_m + mt * 16 + g;
        #pragma unroll
        for (int nt = 0; nt < 4; nt++) {
            int col = n0 + warp_n + nt * 8 + cc;
            if (col < Nc) {
                float2 v0 = make_float2(acc[mt][nt][0], acc[mt][nt][1]);
                float2 v1 = make_float2(acc[mt][nt][2], acc[mt][nt][3]);
                if (R) {
                    float2 r0 = *(const float2*)(R + (size_t)row0 * ldc + col);
                    float2 r1 = *(const float2*)(R + (size_t)(row0 + 8) * ldc + col);
                    v0.x += r0.x; v0.y += r0.y; v1.x += r1.x; v1.y += r1.y;
                }
                *(float2*)(C + (size_t)row0 * ldc + col)       = v0;
                *(float2*)(C + (size_t)(row0 + 8) * ldc + col) = v1;
            }
        }
    }
}

// ---------------- weight transpose + bf16 split ------------------------------
__global__ void wsplit_k(const float* __restrict__ W, __nv_bfloat16* __restrict__ Th,
                         __nv_bfloat16* __restrict__ Tl, int Kd, int Nd, int mode,
                         int Nvalid) {
    __shared__ float t[32][33];
    int n0 = blockIdx.x * 32, k0 = blockIdx.y * 32;
    int tx = threadIdx.x, ty = threadIdx.y;
    #pragma unroll
    for (int i = 0; i < 4; i++)
        t[ty + i * 8][tx] = (n0 + tx < Nvalid)
            ? W[(size_t)(k0 + ty + i * 8) * Nd + n0 + tx] : 0.f;
    __syncthreads();
    #pragma unroll
    for (int i = 0; i < 4; i++) {
        int r = ty + i * 8;
        int n = n0 + r;
        size_t orow = (mode == 0) ? (size_t)n
                    : (size_t)((n >> 6) * 128 + (n & 63) + ((mode == 2) ? 64 : 0));
        float v = t[tx][r];
        __nv_bfloat16 hb = __float2bfloat16(v);
        size_t o = orow * Kd + k0 + tx;
        Th[o] = hb;
        Tl[o] = __float2bfloat16(v - __bfloat162float(hb));
    }
}

// ---------------- rmsnorm -> bf16 split --------------------------------------
__global__ void rmsnorm_k(const float* __restrict__ x, const float* __restrict__ w,
                          __nv_bfloat16* __restrict__ oh, __nv_bfloat16* __restrict__ ol) {
    int row = blockIdx.x;
    const float4* xr = (const float4*)(x + (size_t)row * Dm);
    float4 v = xr[threadIdx.x];
    float ss = v.x*v.x + v.y*v.y + v.z*v.z + v.w*v.w;
    #pragma unroll
    for (int o = 16; o; o >>= 1) ss += __shfl_xor_sync(0xffffffffu, ss, o);
    __shared__ float sws[8];
    int lane = threadIdx.x & 31, wid = threadIdx.x >> 5;
    if (lane == 0) sws[wid] = ss;
    __syncthreads();
    if (threadIdx.x == 0) {
        float t = 0.f;
        #pragma unroll
        for (int i = 0; i < 8; i++) t += sws[i];
        sws[0] = rsqrtf(t * (1.0f / Dm) + 1e-6f);
    }
    __syncthreads();
    float inv = sws[0];
    float4 wv = ((const float4*)w)[threadIdx.x];
    float4 o4;
    o4.x = v.x * inv * wv.x; o4.y = v.y * inv * wv.y;
    o4.z = v.z * inv * wv.z; o4.w = v.w * inv * wv.w;
    __nv_bfloat16 h0 = __float2bfloat16(o4.x), h1 = __float2bfloat16(o4.y);
    __nv_bfloat16 h2 = __float2bfloat16(o4.z), h3 = __float2bfloat16(o4.w);
    __nv_bfloat162 H0; H0.x = h0; H0.y = h1;
    __nv_bfloat162 H1; H1.x = h2; H1.y = h3;
    __nv_bfloat162* ph = (__nv_bfloat162*)(oh + (size_t)row * Dm);
    ph[threadIdx.x * 2]     = H0;
    ph[threadIdx.x * 2 + 1] = H1;
    __nv_bfloat162 L0, L1;
    L0.x = __float2bfloat16(o4.x - __bfloat162float(h0));
    L0.y = __float2bfloat16(o4.y - __bfloat162float(h1));
    L1.x = __float2bfloat16(o4.z - __bfloat162float(h2));
    L1.y = __float2bfloat16(o4.w - __bfloat162float(h3));
    __nv_bfloat162* pl = (__nv_bfloat162*)(ol + (size_t)row * Dm);
    pl[threadIdx.x * 2]     = L0;
    pl[threadIdx.x * 2 + 1] = L1;
}

// ---------------- node/pos + partition starts --------------------------------
__global__ void node_pos_k() {
    int bh = blockIdx.x;
    int b = bh >> 4, h = bh & 15;
    int t = threadIdx.x;
    __shared__ int cnts[256][4];
    __shared__ int base[256][4];
    int myn[8], posl[8];
    int local[4] = {0, 0, 0, 0};
    #pragma unroll
    for (int j = 0; j < 8; j++) {
        int s = t * 8 + j;
        int tok = b * Ss + s;
        const float* lp = g_qkvr + (size_t)tok * NQKV + 3072 + h * 4;
        float l0 = lp[0], l1 = lp[1], l2 = lp[2], l3 = lp[3];
        int n = 0; float bv = l0;
        if (l1 > bv) { bv = l1; n = 1; }
        if (l2 > bv) { bv = l2; n = 2; }
        if (l3 > bv) { bv = l3; n = 3; }
        myn[j] = n;
        posl[j] = local[n];
        local[n]++;
    }
    cnts[t][0] = local[0]; cnts[t][1] = local[1];
    cnts[t][2] = local[2]; cnts[t][3] = local[3];
    __syncthreads();
    if (t == 0) {
        int run[4] = {0, 0, 0, 0};
        for (int i = 0; i < 256; i++)
            #pragma unroll
            for (int v = 0; v < 4; v++) { base[i][v] = run[v]; run[v] += cnts[i][v]; }
        int st = 0;
        #pragma unroll
        for (int v = 0; v < 4; v++) { g_start[bh * 4 + v] = st; st += run[v]; }
    }
    __syncthreads();
    #pragma unroll
    for (int j = 0; j < 8; j++) {
        int s = t * 8 + j;
        int tok = b * Ss + s;
        int n = myn[j];
        g_node[tok * Hh + h] = n;
        g_pos[tok * Hh + h] = (float)(base[t][n] + posl[j]);
    }
}

// ---------------- permute (node partition) + RoPE ----------------------------
__global__ void permute_k() {
    int inst = blockIdx.x * 4 + (threadIdx.x >> 5);   // tok*16 + h
    int lane = threadIdx.x & 31;
    int tok = inst >> 4, h = inst & 15;
    int b = tok >> 11;
    int bh = b * 16 + h;
    int n = g_node[tok * Hh + h];
    float pos = g_pos[tok * Hh + h];
    int startn = g_start[bh * 4 + n];
    int slot = startn + (int)pos;
    const float* src = g_qkvr + (size_t)tok * NQKV;
    float invf = exp2f(-(float)lane * (13.287712379549449f / 32.0f));
    float ang = pos * invf;
    float s, c;
    sincosf(ang, &s, &c);
    size_t drow = ((size_t)bh * Ss + slot) * HDim;
    float q1 = src[h * 64 + lane], q2 = src[h * 64 + lane + 32];
    g_qp[drow + lane]      = q1 * c - q2 * s;
    g_qp[drow + lane + 32] = q2 * c + q1 * s;
    float k1 = src[1024 + h * 64 + lane], k2 = src[1024 + h * 64 + lane + 32];
    g_kp[drow + lane]      = k1 * c - k2 * s;
    g_kp[drow + lane + 32] = k2 * c + k1 * s;
    g_vp[drow + lane]      = src[2048 + h * 64 + lane];
    g_vp[drow + lane + 32] = src[2048 + h * 64 + lane + 32];
    if (lane == 0) {
        g_qstart[bh * Ss + slot] = startn;
        g_orig  [bh * Ss + slot] = tok;
    }
}

// ---------------- attention: maxless single-pass partitioned flash -----------
// Scores bounded (|q|,|k| ~ 8 post-rmsnorm => s <~ 20), so exp(s) never
// overflows fp32 and the max-shift is unnecessary: softmax = exp(s)/sum.
#define ATTN_SMEM ((4096 + 4096) * 4)
__global__ __launch_bounds__(128)
void attn_k() {
    int bh = blockIdx.y;
    int h = bh & 15;
    int q0 = blockIdx.x * 128;
    int tid = threadIdx.x;
    int j = q0 + tid;
    size_t base = (size_t)bh * Ss;
    extern __shared__ float sm[];
    float* Ks = sm;
    float* Vs = sm + 4096;

    float qreg[64];
    const float4* qp = (const float4*)(g_qp + (base + j) * HDim);
    #pragma unroll
    for (int d4 = 0; d4 < 16; d4++) {
        float4 v = qp[d4];
        qreg[d4*4+0] = v.x; qreg[d4*4+1] = v.y; qreg[d4*4+2] = v.z; qreg[d4*4+3] = v.w;
    }
    int startq = g_qstart[base + j];
    int orig   = g_orig[base + j];
    int kt0 = g_qstart[base + q0] >> 6;
    int ktE = (q0 >> 6) + 2;

    float l = 0.f;
    float acc[64];
    #pragma unroll
    for (int d = 0; d < 64; d++) acc[d] = 0.f;

    for (int kt = kt0; kt < ktE; ++kt) {
        int kb = kt * 64;
        __syncthreads();
        for (int e = tid; e < 1024; e += 128) {
            int r = e >> 4, c = (e & 15) * 4;
            size_t srow = (base + kb + r) * HDim;
            *(float4*)&Ks[r * 64 + c] = *(const float4*)(g_kp + srow + c);
            *(float4*)&Vs[r * 64 + c] = *(const float4*)(g_vp + srow + c);
        }
        __syncthreads();

        int kk0 = startq - kb; kk0 = kk0 > 0 ? kk0 : 0;
        int kk1 = j - kb + 1;  kk1 = kk1 < 64 ? kk1 : 64;

        #pragma unroll 1
        for (int kk = kk0; kk < kk1; ++kk) {
            float s0 = 0.f, s1 = 0.f, s2 = 0.f, s3 = 0.f;
            const float4* kr = (const float4*)&Ks[kk * 64];
            #pragma unroll
            for (int d4 = 0; d4 < 16; d4++) {
                float4 kv = kr[d4];
                s0 = fmaf(qreg[d4*4+0], kv.x, s0);
                s1 = fmaf(qreg[d4*4+1], kv.y, s1);
                s2 = fmaf(qreg[d4*4+2], kv.z, s2);
                s3 = fmaf(qreg[d4*4+3], kv.w, s3);
            }
            float p = fexp(((s0 + s1) + (s2 + s3)) * 0.125f);
            l += p;
            const float4* vr = (const float4*)&Vs[kk * 64];
            #pragma unroll
            for (int d4 = 0; d4 < 16; d4++) {
                float4 vv = vr[d4];
                acc[d4*4+0] = fmaf(p, vv.x, acc[d4*4+0]);
                acc[d4*4+1] = fmaf(p, vv.y, acc[d4*4+1]);
                acc[d4*4+2] = fmaf(p, vv.z, acc[d4*4+2]);
                acc[d4*4+3] = fmaf(p, vv.w, acc[d4*4+3]);
            }
        }
    }
    float inv = 1.f / l;
    __nv_bfloat162* oh = (__nv_bfloat162*)(g_cxh + (size_t)orig * Dm + h * HDim);
    __nv_bfloat162* ol = (__nv_bfloat162*)(g_cxl + (size_t)orig * Dm + h * HDim);
    #pragma unroll
    for (int d2 = 0; d2 < 32; d2++) {
        float v0 = acc[d2*2] * inv, v1 = acc[d2*2+1] * inv;
        __nv_bfloat16 h0 = __float2bfloat16(v0), h1 = __float2bfloat16(v1);
        __nv_bfloat162 H; H.x = h0; H.y = h1;
        oh[d2] = H;
        __nv_bfloat162 L;
        L.x = __float2bfloat16(v0 - __bfloat162float(h0));
        L.y = __float2bfloat16(v1 - __bfloat162float(h1));
        ol[d2] = L;
    }
}

// ---------------- host launcher ----------------------------------------------
#define SYM(p, s) do { void* _t; cudaGetSymbolAddress(&_t, s); p = (decltype(p))_t; } while (0)

extern "C" void kernel_launch(void* const* d_in, const int* in_sizes, int n_in,
                              void* d_out, int out_size) {
    const float* x      = (const float*)d_in[0];
    const float* attn_w = (const float*)d_in[1];
    const float* ffn_w  = (const float*)d_in[2];
    const float* Wq     = (const float*)d_in[3];
    const float* Wk     = (const float*)d_in[4];
    const float* Wv     = (const float*)d_in[5];
    const float* Wo     = (const float*)d_in[6];
    const float* Wr     = (const float*)d_in[7];
    const float* w1     = (const float*)d_in[8];
    const float* w2     = (const float*)d_in[9];
    const float* w3     = (const float*)d_in[10];
    float* out = (float*)d_out;

    float *p_qkvr, *p_x2;
    SYM(p_qkvr, g_qkvr); SYM(p_x2, g_x2);
    __nv_bfloat16 *p_hh, *p_hl, *p_cxh, *p_cxl, *p_s1h, *p_s1l;
    SYM(p_hh, g_hh); SYM(p_hl, g_hl); SYM(p_cxh, g_cxh); SYM(p_cxl, g_cxl);
    SYM(p_s1h, g_s1h); SYM(p_s1l, g_s1l);
    __nv_bfloat16 *wAh, *wAl, *woh, *wol, *w12h, *w12l, *w3h, *w3l;
    SYM(wAh, g_wAh); SYM(wAl, g_wAl); SYM(woh, g_woh); SYM(wol, g_wol);
    SYM(w12h, g_w12h); SYM(w12l, g_w12l); SYM(w3h, g_w3h); SYM(w3l, g_w3l);

    cudaFuncSetAttribute(attn_k, cudaFuncAttributeMaxDynamicSharedMemorySize, ATTN_SMEM);
    cudaFuncSetAttribute(gemm_hmma, cudaFuncAttributeMaxDynamicSharedMemorySize, GH_SMEM);

    dim3 tb(32, 8);
    wsplit_k<<<dim3(Dm/32, Dm/32), tb>>>(Wq, wAh,           wAl,           Dm, Dm, 0, Dm);
    wsplit_k<<<dim3(Dm/32, Dm/32), tb>>>(Wk, wAh + 1024*Dm, wAl + 1024*Dm, Dm, Dm, 0, Dm);
    wsplit_k<<<dim3(Dm/32, Dm/32), tb>>>(Wv, wAh + 2048*Dm, wAl + 2048*Dm, Dm, Dm, 0, Dm);
    wsplit_k<<<dim3(4,     Dm/32), tb>>>(Wr, wAh + 3072*Dm, wAl + 3072*Dm, Dm, 64, 0, 64);

    // h = rmsnorm(x) -> bf16 split
    rmsnorm_k<<<TOK, 256>>>(x, attn_w, p_hh, p_hl);

    // fused q|k|v|router GEMM
    gemm_hmma<<<dim3(NQKV/128, TOK/128), 256, GH_SMEM>>>(
        p_hh, p_hl, wAh, wAl, nullptr, p_qkvr, TOK, NQKV, NQKV, Dm,
        nullptr, nullptr, 0);

    // node/pos + partition & rope ; attention
    node_pos_k<<<32, 256>>>();
    permute_k<<<TOK * Hh / 4, 128>>>();
    attn_k<<<dim3(Ss / 128, 2 * Hh), 128, ATTN_SMEM>>>();

    // Wo prep + x2 = x + ctx @ Wo
    wsplit_k<<<dim3(Dm/32, Dm/32), tb>>>(Wo, woh, wol, Dm, Dm, 0, Dm);
    gemm_hmma<<<dim3(Dm/128, TOK/128), 256, GH_SMEM>>>(
        p_cxh, p_cxl, woh, wol, x, p_x2, TOK, Dm, Dm, Dm, nullptr, nullptr, 0);

    // h2 = rmsnorm(x2)
    rmsnorm_k<<<TOK, 256>>>(p_x2, ffn_w, p_hh, p_hl);

    // w1|w2 prep + fused GEMM with SwiGLU epilogue -> s1 (bf16 split)
    wsplit_k<<<dim3(Ff/32, Dm/32), tb>>>(w1, w12h, w12l, Dm, Ff, 1, Ff);
    wsplit_k<<<dim3(Ff/32, Dm/32), tb>>>(w2, w12h, w12l, Dm, Ff, 2, Ff);
    gemm_hmma<<<dim3(2*Ff/128, TOK/128), 256, GH_SMEM>>>(
        p_hh, p_hl, w12h, w12l, nullptr, nullptr, TOK, 2*Ff, 0, Dm,
        p_s1h, p_s1l, 1);

    // w3 prep + out = x2 + s1 @ w3
    wsplit_k<<<dim3(Dm/32, Ff/32), tb>>>(w3, w3h, w3l, Ff, Dm, 0, Dm);
    gemm_hmma<<<dim3(Dm/128, TOK/128), 256, GH_SMEM>>>(
        p_s1h, p_s1l, w3h, w3l, p_x2, out, TOK, Dm, Dm, Ff, nullptr, nullptr, 0);
}

// round 12
// speedup vs baseline: 2.8210x; 1.0153x over previous
#include <cuda_runtime.h>
#include <cuda_bf16.h>
#include <math.h>
#include <math_constants.h>
#include <stdint.h>

#define TOK 4096   // B*S
#define Dm  1024
#define Hh  16
#define HDim 64
#define Ff  4096
#define Ss  2048
#define NQKV 3200  // q(1024) k(1024) v(1024) router(64) pad(64)

// ---------------- fp32 scratch ----------------------------------------------
__device__ float g_qkvr[TOK*NQKV];
__device__ float g_x2 [TOK*Dm];
__device__ int   g_node[TOK*Hh];
__device__ float g_pos [TOK*Hh];
__device__ int   g_start [32*4];
__device__ int   g_qstart[32*Ss];
__device__ int   g_orig  [32*Ss];
__device__ float g_qp[32*Ss*HDim];
__device__ float g_kp[32*Ss*HDim];
__device__ float g_vp[32*Ss*HDim];

// ---------------- bf16 split activations ------------------------------------
__device__ __nv_bfloat16 g_hh [TOK*Dm], g_hl [TOK*Dm];
__device__ __nv_bfloat16 g_cxh[TOK*Dm], g_cxl[TOK*Dm];
__device__ __nv_bfloat16 g_s1h[TOK*Ff], g_s1l[TOK*Ff];

// ---------------- bf16 split transposed weights [N,K] -----------------------
__device__ __nv_bfloat16 g_wAh[NQKV*Dm], g_wAl[NQKV*Dm];    // Wq|Wk|Wv|Wr|0
__device__ __nv_bfloat16 g_woh[Dm*Dm],   g_wol[Dm*Dm];
__device__ __nv_bfloat16 g_w12h[2*Ff*Dm], g_w12l[2*Ff*Dm];  // w1/w2 interleaved
__device__ __nv_bfloat16 g_w3h[Dm*Ff],   g_w3l[Dm*Ff];

// ---------------- helpers -----------------------------------------------------
__device__ __forceinline__ uint32_t s2u(const void* p) {
    uint32_t a;
    asm("{ .reg .u64 t; cvta.to.shared.u64 t, %1; cvt.u32.u64 %0, t; }" : "=r"(a) : "l"(p));
    return a;
}

#define LDSM4(r, addr) \
    asm volatile("ldmatrix.sync.aligned.m8n8.x4.shared.b16 {%0,%1,%2,%3}, [%4];" \
        : "=r"((r)[0]), "=r"((r)[1]), "=r"((r)[2]), "=r"((r)[3]) : "r"(addr))

#define MMA(d, a, b) \
    asm volatile("mma.sync.aligned.m16n8k16.row.col.f32.bf16.bf16.f32 " \
        "{%0,%1,%2,%3}, {%4,%5,%6,%7}, {%8,%9}, {%0,%1,%2,%3};" \
        : "+f"((d)[0]), "+f"((d)[1]), "+f"((d)[2]), "+f"((d)[3]) \
        : "r"((a)[0]), "r"((a)[1]), "r"((a)[2]), "r"((a)[3]), "r"((b)[0]), "r"((b)[1]))

#define CPASYNC(dst, src) \
    asm volatile("cp.async.cg.shared.global [%0], [%1], 16;" :: "r"(dst), "l"(src))

// ---------------- fast exp (FMA pipe only) ----------------------------------
__device__ __forceinline__ float fexp(float x) {
    x = fminf(fmaxf(x, -87.0f), 88.0f);
    float y = x * 1.4426950408889634f;
    float n = rintf(y);
    float f = y - n;
    float p = 1.3333558146e-3f;
    p = fmaf(p, f, 9.6181291076e-3f);
    p = fmaf(p, f, 5.5504108665e-2f);
    p = fmaf(p, f, 2.4022650696e-1f);
    p = fmaf(p, f, 6.9314718056e-1f);
    p = fmaf(p, f, 1.0f);
    return p * __int_as_float(((int)n + 127) << 23);
}

// ---------------- HMMA split-bf16 GEMM, 2-stage, 2 CTAs/SM -------------------
#define BUF_BYTES 40960
#define GH_SMEM   (2 * BUF_BYTES)

__global__ __launch_bounds__(256, 2)
void gemm_hmma(const __nv_bfloat16* __restrict__ Ah, const __nv_bfloat16* __restrict__ Al,
               const __nv_bfloat16* __restrict__ Bh, const __nv_bfloat16* __restrict__ Bl,
               const float* __restrict__ R, float* __restrict__ C,
               int M, int Nc, int ldc, int K,
               __nv_bfloat16* __restrict__ Oh, __nv_bfloat16* __restrict__ Ol, int swiglu) {
    extern __shared__ char smraw[];
    const int tid  = threadIdx.x;
    const int lane = tid & 31, wid = tid >> 5;
    const int m0 = blockIdx.y * 128, n0 = blockIdx.x * 128;
    const int warp_m = (wid >> 2) * 64, warp_n = (wid & 3) * 32;
    const int nc = K >> 5;
    const uint32_t sb = s2u(smraw);

    const char* gA  = (const char*)Ah + (size_t)m0 * K * 2;
    const char* gAl = (const char*)Al + (size_t)m0 * K * 2;
    const char* gB  = (const char*)Bh + (size_t)n0 * K * 2;
    const char* gBl = (const char*)Bl + (size_t)n0 * K * 2;

    int lr0 = tid >> 2,          lc0 = (tid & 3) * 16;
    int lr1 = (tid + 256) >> 2,  lc1 = lc0;

    #define ISSUE(buf, kc) do { \
        uint32_t db = sb + (buf) * BUF_BYTES; \
        size_t ko = (size_t)(kc) * 64; \
        uint32_t so0 = lr0 * 80 + lc0, so1 = lr1 * 80 + lc1; \
        size_t go0 = (size_t)lr0 * (K * 2) + ko + lc0; \
        size_t go1 = (size_t)lr1 * (K * 2) + ko + lc1; \
        CPASYNC(db + so0,         gA  + go0); CPASYNC(db + so1,         gA  + go1); \
        CPASYNC(db + 10240 + so0, gAl + go0); CPASYNC(db + 10240 + so1, gAl + go1); \
        CPASYNC(db + 20480 + so0, gB  + go0); CPASYNC(db + 20480 + so1, gB  + go1); \
        CPASYNC(db + 30720 + so0, gBl + go0); CPASYNC(db + 30720 + so1, gBl + go1); \
        asm volatile("cp.async.commit_group;"); \
    } while (0)

    ISSUE(0, 0);
    ISSUE(1, 1);

    float acc[4][4][4];
    #pragma unroll
    for (int i = 0; i < 4; i++)
        #pragma unroll
        for (int j = 0; j < 4; j++)
            #pragma unroll
            for (int q = 0; q < 4; q++) acc[i][j][q] = 0.f;

    const int a_row = (lane & 7) + ((lane >> 3) & 1) * 8;
    const int a_cb  = (lane >> 4) * 16;
    const int b_row = (lane & 7) + (lane >> 4) * 8;
    const int b_cb  = ((lane >> 3) & 1) * 16;
    const uint32_t aoff = (warp_m + a_row) * 80 + a_cb;
    const uint32_t boff = 20480 + (warp_n + b_row) * 80 + b_cb;

    #pragma unroll 1
    for (int kc = 0; kc < nc; kc++) {
        if (kc + 1 < nc) asm volatile("cp.async.wait_group 1;");
        else             asm volatile("cp.async.wait_group 0;");
        __syncthreads();
        uint32_t db = sb + (kc & 1) * BUF_BYTES;
        #pragma unroll
        for (int ks = 0; ks < 2; ks++) {
            uint32_t ah[4][4], bh[4][2], bl[4][2];
            #pragma unroll
            for (int mt = 0; mt < 4; mt++)
                LDSM4(ah[mt], db + aoff + mt * (16 * 80) + ks * 32);
            #pragma unroll
            for (int p = 0; p < 2; p++) {
                uint32_t bd = db + boff + p * (16 * 80) + ks * 32;
                LDSM4(&bh[2 * p][0], bd);
                LDSM4(&bl[2 * p][0], bd + 10240);
            }
            #pragma unroll
            for (int mt = 0; mt < 4; mt++)
                #pragma unroll
                for (int nt = 0; nt < 4; nt++) MMA(acc[mt][nt], ah[mt], bh[nt]);
            #pragma unroll
            for (int mt = 0; mt < 4; mt++)
                #pragma unroll
                for (int nt = 0; nt < 4; nt++) MMA(acc[mt][nt], ah[mt], bl[nt]);
            uint32_t al[4][4];
            #pragma unroll
            for (int mt = 0; mt < 4; mt++)
                LDSM4(al[mt], db + aoff + mt * (16 * 80) + ks * 32 + 10240);
            #pragma unroll
            for (int mt = 0; mt < 4; mt++)
                #pragma unroll
                for (int nt = 0; nt < 4; nt++) MMA(acc[mt][nt], al[mt], bh[nt]);
        }
        __syncthreads();
        if (kc + 2 < nc) ISSUE(kc & 1, kc + 2);
    }
    #undef ISSUE

    const int g  = lane >> 2;
    const int cc = (lane & 3) * 2;

    if (swiglu) {
        float* sm2 = (float*)smraw;          // [128][68] fp32 staging for a2
        if ((wid & 3) >= 2) {
            #pragma unroll
            for (int mt = 0; mt < 4; mt++) {
                int row0 = warp_m + mt * 16 + g;
                #pragma unroll
                for (int nt = 0; nt < 4; nt++) {
                    int c = warp_n - 64 + nt * 8 + cc;
                    sm2[row0 * 68 + c]           = acc[mt][nt][0];
                    sm2[row0 * 68 + c + 1]       = acc[mt][nt][1];
                    sm2[(row0 + 8) * 68 + c]     = acc[mt][nt][2];
                    sm2[(row0 + 8) * 68 + c + 1] = acc[mt][nt][3];
                }
            }
        }
        __syncthreads();
        if ((wid & 3) < 2) {
            size_t colbase = (size_t)blockIdx.x * 64;
            #pragma unroll
            for (int mt = 0; mt < 4; mt++) {
                #pragma unroll
                for (int rr = 0; rr < 2; rr++) {
                    int row = warp_m + mt * 16 + g + rr * 8;
                    size_t orow = (size_t)(m0 + row) * Ff + colbase;
                    #pragma unroll
                    for (int nt = 0; nt < 4; nt++) {
                        int c = warp_n + nt * 8 + cc;
                        float a1a = acc[mt][nt][rr * 2], a1b = acc[mt][nt][rr * 2 + 1];
                        float a2a = sm2[row * 68 + c], a2b = sm2[row * 68 + c + 1];
                        float r0 = a1a / (1.f + fexp(-a1a)) * a2a;
                        float r1 = a1b / (1.f + fexp(-a1b)) * a2b;
                        __nv_bfloat16 h0 = __float2bfloat16(r0), h1 = __float2bfloat16(r1);
                        __nv_bfloat162 H; H.x = h0; H.y = h1;
                        *(__nv_bfloat162*)(Oh + orow + c) = H;
                        __nv_bfloat162 L;
                        L.x = __float2bfloat16(r0 - __bfloat162float(h0));
                        L.y = __float2bfloat16(r1 - __bfloat162float(h1));
                        *(__nv_bfloat162*)(Ol + orow + c) = L;
                    }
                }
            }
        }
        return;
    }

    #pragma unroll
    for (int mt = 0; mt < 4; mt++) {
        int row0 = m0 + warp_m + mt * 16 + g;
        #pragma unroll
        for (int nt = 0; nt < 4; nt++) {
            int col = n0 + warp_n + nt * 8 + cc;
            if (col < Nc) {
                float2 v0 = make_float2(acc[mt][nt][0], acc[mt][nt][1]);
                float2 v1 = make_float2(acc[mt][nt][2], acc[mt][nt][3]);
                if (R) {
                    float2 r0 = *(const float2*)(R + (size_t)row0 * ldc + col);
                    float2 r1 = *(const float2*)(R + (size_t)(row0 + 8) * ldc + col);
                    v0.x += r0.x; v0.y += r0.y; v1.x += r1.x; v1.y += r1.y;
                }
                *(float2*)(C + (size_t)row0 * ldc + col)       = v0;
                *(float2*)(C + (size_t)(row0 + 8) * ldc + col) = v1;
            }
        }
    }
}

// ---------------- consolidated weight transpose + bf16 split -----------------
// One launch covering Wq|Wk|Wv|Wo|Wr|w1|w2|w3 via flattened block index.
__global__ void wsplit_all(const float* __restrict__ Wq, const float* __restrict__ Wk,
                           const float* __restrict__ Wv, const float* __restrict__ Wo,
                           const float* __restrict__ Wr, const float* __restrict__ w1,
                           const float* __restrict__ w2, const float* __restrict__ w3,
                           __nv_bfloat16* __restrict__ wAh, __nv_bfloat16* __restrict__ wAl,
                           __nv_bfloat16* __restrict__ woh, __nv_bfloat16* __restrict__ wol,
                           __nv_bfloat16* __restrict__ w12h, __nv_bfloat16* __restrict__ w12l,
                           __nv_bfloat16* __restrict__ w3h, __nv_bfloat16* __restrict__ w3l) {
    int idx = blockIdx.x;
    const float* W;
    __nv_bfloat16 *Th, *Tl;
    int Kd, Nd, mode, Nvalid, bx, by;
    if (idx < 4096) {                      // Wq,Wk,Wv,Wo: 1024 blocks each
        int which = idx >> 10, local = idx & 1023;
        bx = local & 31; by = local >> 5;
        Kd = Dm; Nd = Dm; mode = 0; Nvalid = Dm;
        if      (which == 0) { W = Wq; Th = wAh;             Tl = wAl; }
        else if (which == 1) { W = Wk; Th = wAh + 1024*Dm;   Tl = wAl + 1024*Dm; }
        else if (which == 2) { W = Wv; Th = wAh + 2048*Dm;   Tl = wAl + 2048*Dm; }
        else                 { W = Wo; Th = woh;             Tl = wol; }
    } else if (idx < 4224) {               // Wr: 4 x 32 blocks (incl. pad cols)
        int local = idx - 4096;
        bx = local & 3; by = local >> 2;
        W = Wr; Th = wAh + (size_t)3072*Dm; Tl = wAl + (size_t)3072*Dm;
        Kd = Dm; Nd = 64; mode = 0; Nvalid = 64;
    } else if (idx < 8320) {               // w1: 128 x 32 blocks
        int local = idx - 4224;
        bx = local & 127; by = local >> 7;
        W = w1; Th = w12h; Tl = w12l; Kd = Dm; Nd = Ff; mode = 1; Nvalid = Ff;
    } else if (idx < 12416) {              // w2: 128 x 32 blocks
        int local = idx - 8320;
        bx = local & 127; by = local >> 7;
        W = w2; Th = w12h; Tl = w12l; Kd = Dm; Nd = Ff; mode = 2; Nvalid = Ff;
    } else {                               // w3: 32 x 128 blocks
        int local = idx - 12416;
        bx = local & 31; by = local >> 5;
        W = w3; Th = w3h; Tl = w3l; Kd = Ff; Nd = Dm; mode = 0; Nvalid = Dm;
    }

    __shared__ float t[32][33];
    int n0 = bx * 32, k0 = by * 32;
    int tx = threadIdx.x, ty = threadIdx.y;
    #pragma unroll
    for (int i = 0; i < 4; i++)
        t[ty + i * 8][tx] = (n0 + tx < Nvalid)
            ? W[(size_t)(k0 + ty + i * 8) * Nd + n0 + tx] : 0.f;
    __syncthreads();
    #pragma unroll
    for (int i = 0; i < 4; i++) {
        int r = ty + i * 8;
        int n = n0 + r;
        size_t orow = (mode == 0) ? (size_t)n
                    : (size_t)((n >> 6) * 128 + (n & 63) + ((mode == 2) ? 64 : 0));
        float v = t[tx][r];
        __nv_bfloat16 hb = __float2bfloat16(v);
        size_t o = orow * Kd + k0 + tx;
        Th[o] = hb;
        Tl[o] = __float2bfloat16(v - __bfloat162float(hb));
    }
}

// ---------------- rmsnorm -> bf16 split --------------------------------------
__global__ void rmsnorm_k(const float* __restrict__ x, const float* __restrict__ w,
                          __nv_bfloat16* __restrict__ oh, __nv_bfloat16* __restrict__ ol) {
    int row = blockIdx.x;
    const float4* xr = (const float4*)(x + (size_t)row * Dm);
    float4 v = xr[threadIdx.x];
    float ss = v.x*v.x + v.y*v.y + v.z*v.z + v.w*v.w;
    #pragma unroll
    for (int o = 16; o; o >>= 1) ss += __shfl_xor_sync(0xffffffffu, ss, o);
    __shared__ float sws[8];
    int lane = threadIdx.x & 31, wid = threadIdx.x >> 5;
    if (lane == 0) sws[wid] = ss;
    __syncthreads();
    if (threadIdx.x == 0) {
        float t = 0.f;
        #pragma unroll
        for (int i = 0; i < 8; i++) t += sws[i];
        sws[0] = rsqrtf(t * (1.0f / Dm) + 1e-6f);
    }
    __syncthreads();
    float inv = sws[0];
    float4 wv = ((const float4*)w)[threadIdx.x];
    float4 o4;
    o4.x = v.x * inv * wv.x; o4.y = v.y * inv * wv.y;
    o4.z = v.z * inv * wv.z; o4.w = v.w * inv * wv.w;
    __nv_bfloat16 h0 = __float2bfloat16(o4.x), h1 = __float2bfloat16(o4.y);
    __nv_bfloat16 h2 = __float2bfloat16(o4.z), h3 = __float2bfloat16(o4.w);
    __nv_bfloat162 H0; H0.x = h0; H0.y = h1;
    __nv_bfloat162 H1; H1.x = h2; H1.y = h3;
    __nv_bfloat162* ph = (__nv_bfloat162*)(oh + (size_t)row * Dm);
    ph[threadIdx.x * 2]     = H0;
    ph[threadIdx.x * 2 + 1] = H1;
    __nv_bfloat162 L0, L1;
    L0.x = __float2bfloat16(o4.x - __bfloat162float(h0));
    L0.y = __float2bfloat16(o4.y - __bfloat162float(h1));
    L1.x = __float2bfloat16(o4.z - __bfloat162float(h2));
    L1.y = __float2bfloat16(o4.w - __bfloat162float(h3));
    __nv_bfloat162* pl = (__nv_bfloat162*)(ol + (size_t)row * Dm);
    pl[threadIdx.x * 2]     = L0;
    pl[threadIdx.x * 2 + 1] = L1;
}

// ---------------- node/pos + partition starts (parallel scan) ----------------
__global__ void node_pos_k() {
    int bh = blockIdx.x;
    int b = bh >> 4, h = bh & 15;
    int t = threadIdx.x;
    int lane = t & 31, wid = t >> 5;
    __shared__ int cnts[256][4];
    __shared__ int base[256][4];
    __shared__ int tot[4];
    int myn[8], posl[8];
    int local[4] = {0, 0, 0, 0};
    #pragma unroll
    for (int j = 0; j < 8; j++) {
        int s = t * 8 + j;
        int tok = b * Ss + s;
        const float* lp = g_qkvr + (size_t)tok * NQKV + 3072 + h * 4;
        float l0 = lp[0], l1 = lp[1], l2 = lp[2], l3 = lp[3];
        int n = 0; float bv = l0;
        if (l1 > bv) { bv = l1; n = 1; }
        if (l2 > bv) { bv = l2; n = 2; }
        if (l3 > bv) { bv = l3; n = 3; }
        myn[j] = n;
        posl[j] = local[n];
        local[n]++;
    }
    cnts[t][0] = local[0]; cnts[t][1] = local[1];
    cnts[t][2] = local[2]; cnts[t][3] = local[3];
    __syncthreads();
    if (wid < 4) {                     // warp v scans column v (256 entries)
        int v = wid;
        int vals[8], part = 0;
        #pragma unroll
        for (int m = 0; m < 8; m++) { vals[m] = cnts[lane * 8 + m][v]; part += vals[m]; }
        int scan = part;
        #pragma unroll
        for (int o = 1; o < 32; o <<= 1) {
            int u = __shfl_up_sync(0xffffffffu, scan, o);
            if (lane >= o) scan += u;
        }
        int excl = scan - part;
        int run = 0;
        #pragma unroll
        for (int m = 0; m < 8; m++) { base[lane * 8 + m][v] = excl + run; run += vals[m]; }
        if (lane == 31) tot[v] = excl + part;
    }
    __syncthreads();
    if (t == 0) {
        int st = 0;
        #pragma unroll
        for (int v = 0; v < 4; v++) { g_start[bh * 4 + v] = st; st += tot[v]; }
    }
    __syncthreads();
    #pragma unroll
    for (int j = 0; j < 8; j++) {
        int s = t * 8 + j;
        int tok = b * Ss + s;
        int n = myn[j];
        g_node[tok * Hh + h] = n;
        g_pos[tok * Hh + h] = (float)(base[t][n] + posl[j]);
    }
}

// ---------------- permute (node partition) + RoPE ----------------------------
__global__ void permute_k() {
    int inst = blockIdx.x * 8 + (threadIdx.x >> 5);   // tok*16 + h
    int lane = threadIdx.x & 31;
    int tok = inst >> 4, h = inst & 15;
    int b = tok >> 11;
    int bh = b * 16 + h;
    int n = g_node[tok * Hh + h];
    float pos = g_pos[tok * Hh + h];
    int startn = g_start[bh * 4 + n];
    int slot = startn + (int)pos;
    const float* src = g_qkvr + (size_t)tok * NQKV;
    float invf = exp2f(-(float)lane * (13.287712379549449f / 32.0f));
    float ang = pos * invf;
    float s, c;
    sincosf(ang, &s, &c);
    size_t drow = ((size_t)bh * Ss + slot) * HDim;
    float q1 = src[h * 64 + lane], q2 = src[h * 64 + lane + 32];
    g_qp[drow + lane]      = q1 * c - q2 * s;
    g_qp[drow + lane + 32] = q2 * c + q1 * s;
    float k1 = src[1024 + h * 64 + lane], k2 = src[1024 + h * 64 + lane + 32];
    g_kp[drow + lane]      = k1 * c - k2 * s;
    g_kp[drow + lane + 32] = k2 * c + k1 * s;
    g_vp[drow + lane]      = src[2048 + h * 64 + lane];
    g_vp[drow + lane + 32] = src[2048 + h * 64 + lane + 32];
    if (lane == 0) {
        g_qstart[bh * Ss + slot] = startn;
        g_orig  [bh * Ss + slot] = tok;
    }
}

// ---------------- attention: maxless single-pass partitioned flash -----------
#define ATTN_SMEM ((4096 + 4096) * 4)
__global__ __launch_bounds__(128)
void attn_k() {
    int bh = blockIdx.y;
    int h = bh & 15;
    int q0 = blockIdx.x * 128;
    int tid = threadIdx.x;
    int j = q0 + tid;
    size_t base = (size_t)bh * Ss;
    extern __shared__ float sm[];
    float* Ks = sm;
    float* Vs = sm + 4096;

    float qreg[64];
    const float4* qp = (const float4*)(g_qp + (base + j) * HDim);
    #pragma unroll
    for (int d4 = 0; d4 < 16; d4++) {
        float4 v = qp[d4];
        qreg[d4*4+0] = v.x; qreg[d4*4+1] = v.y; qreg[d4*4+2] = v.z; qreg[d4*4+3] = v.w;
    }
    int startq = g_qstart[base + j];
    int orig   = g_orig[base + j];
    int kt0 = g_qstart[base + q0] >> 6;
    int ktE = (q0 >> 6) + 2;

    float l = 0.f;
    float acc[64];
    #pragma unroll
    for (int d = 0; d < 64; d++) acc[d] = 0.f;

    for (int kt = kt0; kt < ktE; ++kt) {
        int kb = kt * 64;
        __syncthreads();
        for (int e = tid; e < 1024; e += 128) {
            int r = e >> 4, c = (e & 15) * 4;
            size_t srow = (base + kb + r) * HDim;
            *(float4*)&Ks[r * 64 + c] = *(const float4*)(g_kp + srow + c);
            *(float4*)&Vs[r * 64 + c] = *(const float4*)(g_vp + srow + c);
        }
        __syncthreads();

        int kk0 = startq - kb; kk0 = kk0 > 0 ? kk0 : 0;
        int kk1 = j - kb + 1;  kk1 = kk1 < 64 ? kk1 : 64;

        #pragma unroll 1
        for (int kk = kk0; kk < kk1; ++kk) {
            float s0 = 0.f, s1 = 0.f, s2 = 0.f, s3 = 0.f;
            const float4* kr = (const float4*)&Ks[kk * 64];
            #pragma unroll
            for (int d4 = 0; d4 < 16; d4++) {
                float4 kv = kr[d4];
                s0 = fmaf(qreg[d4*4+0], kv.x, s0);
                s1 = fmaf(qreg[d4*4+1], kv.y, s1);
                s2 = fmaf(qreg[d4*4+2], kv.z, s2);
                s3 = fmaf(qreg[d4*4+3], kv.w, s3);
            }
            float p = fexp(((s0 + s1) + (s2 + s3)) * 0.125f);
            l += p;
            const float4* vr = (const float4*)&Vs[kk * 64];
            #pragma unroll
            for (int d4 = 0; d4 < 16; d4++) {
                float4 vv = vr[d4];
                acc[d4*4+0] = fmaf(p, vv.x, acc[d4*4+0]);
                acc[d4*4+1] = fmaf(p, vv.y, acc[d4*4+1]);
                acc[d4*4+2] = fmaf(p, vv.z, acc[d4*4+2]);
                acc[d4*4+3] = fmaf(p, vv.w, acc[d4*4+3]);
            }
        }
    }
    float inv = 1.f / l;
    __nv_bfloat162* oh = (__nv_bfloat162*)(g_cxh + (size_t)orig * Dm + h * HDim);
    __nv_bfloat162* ol = (__nv_bfloat162*)(g_cxl + (size_t)orig * Dm + h * HDim);
    #pragma unroll
    for (int d2 = 0; d2 < 32; d2++) {
        float v0 = acc[d2*2] * inv, v1 = acc[d2*2+1] * inv;
        __nv_bfloat16 h0 = __float2bfloat16(v0), h1 = __float2bfloat16(v1);
        __nv_bfloat162 H; H.x = h0; H.y = h1;
        oh[d2] = H;
        __nv_bfloat162 L;
        L.x = __float2bfloat16(v0 - __bfloat162float(h0));
        L.y = __float2bfloat16(v1 - __bfloat162float(h1));
        ol[d2] = L;
    }
}

// ---------------- host launcher ----------------------------------------------
#define SYM(p, s) do { void* _t; cudaGetSymbolAddress(&_t, s); p = (decltype(p))_t; } while (0)

extern "C" void kernel_launch(void* const* d_in, const int* in_sizes, int n_in,
                              void* d_out, int out_size) {
    const float* x      = (const float*)d_in[0];
    const float* attn_w = (const float*)d_in[1];
    const float* ffn_w  = (const float*)d_in[2];
    const float* Wq     = (const float*)d_in[3];
    const float* Wk     = (const float*)d_in[4];
    const float* Wv     = (const float*)d_in[5];
    const float* Wo     = (const float*)d_in[6];
    const float* Wr     = (const float*)d_in[7];
    const float* w1     = (const float*)d_in[8];
    const float* w2     = (const float*)d_in[9];
    const float* w3     = (const float*)d_in[10];
    float* out = (float*)d_out;

    float *p_qkvr, *p_x2;
    SYM(p_qkvr, g_qkvr); SYM(p_x2, g_x2);
    __nv_bfloat16 *p_hh, *p_hl, *p_cxh, *p_cxl, *p_s1h, *p_s1l;
    SYM(p_hh, g_hh); SYM(p_hl, g_hl); SYM(p_cxh, g_cxh); SYM(p_cxl, g_cxl);
    SYM(p_s1h, g_s1h); SYM(p_s1l, g_s1l);
    __nv_bfloat16 *wAh, *wAl, *woh, *wol, *w12h, *w12l, *w3h, *w3l;
    SYM(wAh, g_wAh); SYM(wAl, g_wAl); SYM(woh, g_woh); SYM(wol, g_wol);
    SYM(w12h, g_w12h); SYM(w12l, g_w12l); SYM(w3h, g_w3h); SYM(w3l, g_w3l);

    cudaFuncSetAttribute(attn_k, cudaFuncAttributeMaxDynamicSharedMemorySize, ATTN_SMEM);
    cudaFuncSetAttribute(gemm_hmma, cudaFuncAttributeMaxDynamicSharedMemorySize, GH_SMEM);

    // single consolidated weight-prep launch (16512 blocks)
    wsplit_all<<<16512, dim3(32, 8)>>>(Wq, Wk, Wv, Wo, Wr, w1, w2, w3,
                                       wAh, wAl, woh, wol, w12h, w12l, w3h, w3l);

    // h = rmsnorm(x) -> bf16 split
    rmsnorm_k<<<TOK, 256>>>(x, attn_w, p_hh, p_hl);

    // fused q|k|v|router GEMM
    gemm_hmma<<<dim3(NQKV/128, TOK/128), 256, GH_SMEM>>>(
        p_hh, p_hl, wAh, wAl, nullptr, p_qkvr, TOK, NQKV, NQKV, Dm,
        nullptr, nullptr, 0);

    // node/pos + partition & rope ; attention
    node_pos_k<<<32, 256>>>();
    permute_k<<<TOK * Hh / 8, 256>>>();
    attn_k<<<dim3(Ss / 128, 2 * Hh), 128, ATTN_SMEM>>>();

    // x2 = x + ctx @ Wo
    gemm_hmma<<<dim3(Dm/128, TOK/128), 256, GH_SMEM>>>(
        p_cxh, p_cxl, woh, wol, x, p_x2, TOK, Dm, Dm, Dm, nullptr, nullptr, 0);

    // h2 = rmsnorm(x2)
    rmsnorm_k<<<TOK, 256>>>(p_x2, ffn_w, p_hh, p_hl);

    // fused w1|w2 GEMM with SwiGLU epilogue -> s1 (bf16 split)
    gemm_hmma<<<dim3(2*Ff/128, TOK/128), 256, GH_SMEM>>>(
        p_hh, p_hl, w12h, w12l, nullptr, nullptr, TOK, 2*Ff, 0, Dm,
        p_s1h, p_s1l, 1);

    // out = x2 + s1 @ w3
    gemm_hmma<<<dim3(Dm/128, TOK/128), 256, GH_SMEM>>>(
        p_s1h, p_s1l, w3h, w3l, p_x2, out, TOK, Dm, Dm, Ff, nullptr, nullptr, 0);
}